// round 3
// baseline (speedup 1.0000x reference)
#include <cuda_runtime.h>

// Problem constants (fixed by the dataset)
#define B_  16
#define H_  12
#define N_  576
#define D_  64
#define C_  768
#define GW_ 24    // grid width == height == 24, N = 24*24

// ---- scratch (static __device__ arrays: allocation-free) ----
__device__ float g_Q [B_*H_*N_*D_];   // [B,h,N,d]  28.3 MB
__device__ float g_K [B_*H_*N_*D_];
__device__ float g_V [B_*H_*N_*D_];
__device__ float g_AO[B_*N_*C_];      // attention output, [B,N,C] layout
__device__ float g_SP[H_*N_*N_];      // positional softmax table, 15.9 MB (L2-resident)

// ============================================================================
// K1: QKV GEMM.  C[9216,768] = x[9216,768] @ W[768,768], scattered to
// head-major [B,h,N,d] layout. grid.z selects Wq/Wk/Wv.
// 64x64 tile, 256 threads, 4x4 micro-tile, K-step 16.
// ============================================================================
__global__ __launch_bounds__(256) void qkv_kernel(
    const float* __restrict__ x,
    const float* __restrict__ Wq,
    const float* __restrict__ Wk,
    const float* __restrict__ Wv)
{
    const float* W  = (blockIdx.z == 0) ? Wq : (blockIdx.z == 1) ? Wk : Wv;
    float*       dst = (blockIdx.z == 0) ? g_Q : (blockIdx.z == 1) ? g_K : g_V;

    __shared__ __align__(16) float sA[16][68];   // [k][row], stride 68 keeps 16B align
    __shared__ __align__(16) float sB[16][68];   // [k][col]

    const int t   = threadIdx.x;
    const int tr  = t & 15;        // micro-tile rows 4*tr..+3
    const int tc  = t >> 4;        // micro-tile cols 4*tc..+3
    const int row0 = blockIdx.x * 64;
    const int col0 = blockIdx.y * 64;

    const int ar = t >> 2, ak = (t & 3) << 2;      // A-tile load map
    const int bk = t >> 4, bc = (t & 15) << 2;     // B-tile load map

    float acc[4][4] = {};

    for (int k0 = 0; k0 < C_; k0 += 16) {
        float4 av = *(const float4*)&x[(row0 + ar) * C_ + k0 + ak];
        float4 bv = *(const float4*)&W[(k0 + bk) * C_ + col0 + bc];
        sA[ak + 0][ar] = av.x; sA[ak + 1][ar] = av.y;
        sA[ak + 2][ar] = av.z; sA[ak + 3][ar] = av.w;
        *(float4*)&sB[bk][bc] = bv;
        __syncthreads();

        #pragma unroll
        for (int kk = 0; kk < 16; kk++) {
            float4 a = *(float4*)&sA[kk][tr * 4];
            float4 b = *(float4*)&sB[kk][tc * 4];
            float ax[4] = {a.x, a.y, a.z, a.w};
            float bx[4] = {b.x, b.y, b.z, b.w};
            #pragma unroll
            for (int i = 0; i < 4; i++)
                #pragma unroll
                for (int j = 0; j < 4; j++)
                    acc[i][j] += ax[i] * bx[j];
        }
        __syncthreads();
    }

    // scatter into [B,h,N,d]
    #pragma unroll
    for (int i = 0; i < 4; i++) {
        int row = row0 + 4 * tr + i;
        int b   = row / N_;
        int n   = row - b * N_;
        #pragma unroll
        for (int j = 0; j < 4; j++) {
            int col = col0 + 4 * tc + j;
            int hh  = col >> 6;
            int dd  = col & 63;
            dst[(((b * H_ + hh) * N_) + n) * D_ + dd] = acc[i][j];
        }
    }
}

// ============================================================================
// K2: positional softmax table S_pos[h][n][m].  One warp per (h,n) row.
// Scores computed analytically from (dx,dy,dx^2+dy^2).
// ============================================================================
__global__ __launch_bounds__(256) void pos_kernel(
    const float* __restrict__ pos_w,   // [3,12] row-major
    const float* __restrict__ pos_b)   // [12]
{
    const int warp = threadIdx.x >> 5;
    const int lane = threadIdx.x & 31;
    const int row  = blockIdx.x * 8 + warp;        // 0 .. 12*576-1
    const int h    = row / N_;
    const int n    = row - h * N_;

    const float wx = pos_w[0 * H_ + h];
    const float wy = pos_w[1 * H_ + h];
    const float wz = pos_w[2 * H_ + h];
    const float pb = pos_b[h];
    const int nx = n % GW_, ny = n / GW_;

    float buf[18];
    float mx = -1e30f;
    #pragma unroll
    for (int i = 0; i < 18; i++) {
        int m  = lane + 32 * i;
        int dx = (m % GW_) - nx;
        int dy = (m / GW_) - ny;
        float fdx = (float)dx, fdy = (float)dy;
        float s = wx * fdx + wy * fdy + wz * (fdx * fdx + fdy * fdy) + pb;
        buf[i] = s;
        mx = fmaxf(mx, s);
    }
    #pragma unroll
    for (int o = 16; o; o >>= 1) mx = fmaxf(mx, __shfl_xor_sync(0xffffffffu, mx, o));

    float sum = 0.f;
    #pragma unroll
    for (int i = 0; i < 18; i++) { buf[i] = __expf(buf[i] - mx); sum += buf[i]; }
    #pragma unroll
    for (int o = 16; o; o >>= 1) sum += __shfl_xor_sync(0xffffffffu, sum, o);

    const float inv = 1.f / sum;
    float* dstp = g_SP + (size_t)row * N_;
    #pragma unroll
    for (int i = 0; i < 18; i++) dstp[lane + 32 * i] = buf[i] * inv;
}

// ============================================================================
// K3: fused attention. One block = (b, h, 32 query rows). 256 threads.
//   A) scores[32][576] = Q32x64 @ K^T (d=64 fully resident) -> SMEM strip
//   B) per-row max & sumexp (warp-per-row)
//   C) w = (1-g)*softmax(s) + g*S_pos   (S_pos read from L2)
//   D) out[32][64] = w @ V
// Renormalization skipped (sums to 1 analytically).
// ============================================================================
#define SQT_STRIDE 33
#define SKV_STRIDE 68
#define SS_STRIDE  577
#define ATTN_SMEM_FLOATS (64*SQT_STRIDE + 64*SKV_STRIDE + 32*SS_STRIDE + 64)

__global__ __launch_bounds__(256) void attn_kernel(const float* __restrict__ gating)
{
    extern __shared__ __align__(16) float sm[];
    float* sQt  = sm;                              // [d][n] 64 x 33
    float* sKV  = sQt + 64 * SQT_STRIDE;           // K^T [d][m] or V [m][d], 64 x 68
    float* sS   = sKV + 64 * SKV_STRIDE;           // scores/weights 32 x 577
    float* rMax = sS  + 32 * SS_STRIDE;            // [32]
    float* rInv = rMax + 32;                       // [32]

    const int b  = blockIdx.z;
    const int h  = blockIdx.y;
    const int n0 = blockIdx.x * 32;
    const int t  = threadIdx.x;
    const int tr = t >> 4;        // 0..15 -> rows 2*tr, 2*tr+1
    const int tc = t & 15;        // cols 4*tc..+3

    const float* Qp = g_Q + (((size_t)(b * H_ + h)) * N_ + n0) * D_;
    const float* Kp = g_K + ((size_t)(b * H_ + h)) * N_ * D_;
    const float* Vp = g_V + ((size_t)(b * H_ + h)) * N_ * D_;

    // load Q tile transposed: sQt[d][n]
    for (int i = t; i < 32 * 16; i += 256) {       // 512 float4
        int n  = i >> 4;
        int d4 = (i & 15) << 2;
        float4 v = *(const float4*)&Qp[n * D_ + d4];
        sQt[(d4 + 0) * SQT_STRIDE + n] = v.x;
        sQt[(d4 + 1) * SQT_STRIDE + n] = v.y;
        sQt[(d4 + 2) * SQT_STRIDE + n] = v.z;
        sQt[(d4 + 3) * SQT_STRIDE + n] = v.w;
    }

    // ---------------- Phase A: scores ----------------
    for (int m0 = 0; m0 < N_; m0 += 64) {
        __syncthreads();
        // load K tile transposed: sKV[d][m]
        for (int i = t; i < 64 * 16; i += 256) {
            int m  = i >> 4;
            int d4 = (i & 15) << 2;
            float4 v = *(const float4*)&Kp[(m0 + m) * D_ + d4];
            sKV[(d4 + 0) * SKV_STRIDE + m] = v.x;
            sKV[(d4 + 1) * SKV_STRIDE + m] = v.y;
            sKV[(d4 + 2) * SKV_STRIDE + m] = v.z;
            sKV[(d4 + 3) * SKV_STRIDE + m] = v.w;
        }
        __syncthreads();

        float s0[4] = {}, s1[4] = {};
        #pragma unroll 16
        for (int d = 0; d < 64; d++) {
            float a0 = sQt[d * SQT_STRIDE + 2 * tr];
            float a1 = sQt[d * SQT_STRIDE + 2 * tr + 1];
            #pragma unroll
            for (int j = 0; j < 4; j++) {
                float bb = sKV[d * SKV_STRIDE + 4 * tc + j];
                s0[j] += a0 * bb;
                s1[j] += a1 * bb;
            }
        }
        #pragma unroll
        for (int j = 0; j < 4; j++) {
            sS[(2 * tr    ) * SS_STRIDE + m0 + 4 * tc + j] = s0[j] * 0.125f;
            sS[(2 * tr + 1) * SS_STRIDE + m0 + 4 * tc + j] = s1[j] * 0.125f;
        }
    }
    __syncthreads();

    // ---------------- Phase B: row stats ----------------
    {
        const int warp = t >> 5, lane = t & 31;
        for (int r = warp; r < 32; r += 8) {
            const float* rowp = sS + r * SS_STRIDE;
            float mx = -1e30f;
            for (int m = lane; m < N_; m += 32) mx = fmaxf(mx, rowp[m]);
            #pragma unroll
            for (int o = 16; o; o >>= 1) mx = fmaxf(mx, __shfl_xor_sync(0xffffffffu, mx, o));
            float sum = 0.f;
            for (int m = lane; m < N_; m += 32) sum += __expf(rowp[m] - mx);
            #pragma unroll
            for (int o = 16; o; o >>= 1) sum += __shfl_xor_sync(0xffffffffu, sum, o);
            if (lane == 0) { rMax[r] = mx; rInv[r] = 1.f / sum; }
        }
    }
    __syncthreads();

    // ---------------- Phase C: combine with positional ----------------
    {
        const float gt = 1.f / (1.f + __expf(-gating[h]));
        const float c1 = 1.f - gt;
        const float* SP = g_SP + ((size_t)h * N_ + n0) * N_;
        for (int j = t; j < 32 * N_; j += 256) {
            int n = j / N_;
            int m = j - n * N_;
            float p = __expf(sS[n * SS_STRIDE + m] - rMax[n]) * rInv[n];
            sS[n * SS_STRIDE + m] = c1 * p + gt * SP[n * N_ + m];
        }
    }

    // ---------------- Phase D: out = w @ V ----------------
    float acc0[4] = {}, acc1[4] = {};
    for (int m0 = 0; m0 < N_; m0 += 64) {
        __syncthreads();
        // load V tile: sKV[m][d]
        for (int i = t; i < 64 * 16; i += 256) {
            int m  = i >> 4;
            int d4 = (i & 15) << 2;
            float4 v = *(const float4*)&Vp[(m0 + m) * D_ + d4];
            *(float4*)&sKV[m * SKV_STRIDE + d4] = v;
        }
        __syncthreads();

        #pragma unroll 16
        for (int m = 0; m < 64; m++) {
            float w0 = sS[(2 * tr    ) * SS_STRIDE + m0 + m];
            float w1 = sS[(2 * tr + 1) * SS_STRIDE + m0 + m];
            #pragma unroll
            for (int j = 0; j < 4; j++) {
                float vv = sKV[m * SKV_STRIDE + 4 * tc + j];
                acc0[j] += w0 * vv;
                acc1[j] += w1 * vv;
            }
        }
    }

    float* Op = g_AO + ((size_t)(b * N_ + n0)) * C_ + h * D_;
    #pragma unroll
    for (int j = 0; j < 4; j++) {
        Op[(2 * tr    ) * C_ + 4 * tc + j] = acc0[j];
        Op[(2 * tr + 1) * C_ + 4 * tc + j] = acc1[j];
    }
}

// ============================================================================
// K4: projection GEMM. out[9216,768] = g_AO @ Wproj + bproj
// ============================================================================
__global__ __launch_bounds__(256) void proj_kernel(
    const float* __restrict__ Wproj,
    const float* __restrict__ bproj,
    float* __restrict__ out)
{
    __shared__ __align__(16) float sA[16][68];
    __shared__ __align__(16) float sB[16][68];

    const int t = threadIdx.x;
    const int tr = t & 15, tc = t >> 4;
    const int row0 = blockIdx.x * 64;
    const int col0 = blockIdx.y * 64;
    const int ar = t >> 2, ak = (t & 3) << 2;
    const int bk = t >> 4, bc = (t & 15) << 2;

    float acc[4][4] = {};

    for (int k0 = 0; k0 < C_; k0 += 16) {
        float4 av = *(const float4*)&g_AO[(size_t)(row0 + ar) * C_ + k0 + ak];
        float4 bv = *(const float4*)&Wproj[(k0 + bk) * C_ + col0 + bc];
        sA[ak + 0][ar] = av.x; sA[ak + 1][ar] = av.y;
        sA[ak + 2][ar] = av.z; sA[ak + 3][ar] = av.w;
        *(float4*)&sB[bk][bc] = bv;
        __syncthreads();

        #pragma unroll
        for (int kk = 0; kk < 16; kk++) {
            float4 a = *(float4*)&sA[kk][tr * 4];
            float4 b = *(float4*)&sB[kk][tc * 4];
            float ax[4] = {a.x, a.y, a.z, a.w};
            float bx[4] = {b.x, b.y, b.z, b.w};
            #pragma unroll
            for (int i = 0; i < 4; i++)
                #pragma unroll
                for (int j = 0; j < 4; j++)
                    acc[i][j] += ax[i] * bx[j];
        }
        __syncthreads();
    }

    #pragma unroll
    for (int i = 0; i < 4; i++) {
        int row = row0 + 4 * tr + i;
        #pragma unroll
        for (int j = 0; j < 4; j++) {
            int col = col0 + 4 * tc + j;
            out[(size_t)row * C_ + col] = acc[i][j] + bproj[col];
        }
    }
}

// ============================================================================
extern "C" void kernel_launch(void* const* d_in, const int* in_sizes, int n_in,
                              void* d_out, int out_size)
{
    const float* x      = (const float*)d_in[0];
    const float* Wq     = (const float*)d_in[1];
    const float* Wk     = (const float*)d_in[2];
    const float* Wv     = (const float*)d_in[3];
    const float* Wproj  = (const float*)d_in[4];
    const float* bproj  = (const float*)d_in[5];
    const float* pos_w  = (const float*)d_in[6];
    const float* pos_b  = (const float*)d_in[7];
    const float* gating = (const float*)d_in[8];
    float* out = (float*)d_out;

    const size_t attn_smem = ATTN_SMEM_FLOATS * sizeof(float);   // ~99.9 KB
    cudaFuncSetAttribute(attn_kernel, cudaFuncAttributeMaxDynamicSharedMemorySize,
                         (int)attn_smem);

    // K1: QKV (z=0/1/2 -> Q/K/V)
    qkv_kernel<<<dim3(C_ * B_ * N_ / C_ / 64, C_ / 64, 3), 256>>>(x, Wq, Wk, Wv);
    // K2: positional softmax table (independent of K1)
    pos_kernel<<<(H_ * N_) / 8, 256>>>(pos_w, pos_b);
    // K3: fused attention
    attn_kernel<<<dim3(N_ / 32, H_, B_), 256, attn_smem>>>(gating);
    // K4: projection
    proj_kernel<<<dim3(B_ * N_ / 64, C_ / 64), 256>>>(Wproj, bproj, out);
}

// round 7
// speedup vs baseline: 1.6374x; 1.6374x over previous
#include <cuda_runtime.h>

typedef unsigned int u32;

// Problem constants (fixed by the dataset)
#define B_  16
#define H_  12
#define N_  576
#define D_  64
#define C_  768
#define GW_ 24

// ---- scratch ----
__device__ float g_Q [B_*H_*N_*D_];
__device__ float g_K [B_*H_*N_*D_];
__device__ float g_V [B_*H_*N_*D_];
__device__ float g_AO[B_*N_*C_];
__device__ float g_SP[H_*N_*N_];      // positional softmax table (L2-resident, 15.9MB)

// ---------------------------------------------------------------------------
// TF32 helpers
// ---------------------------------------------------------------------------
__device__ __forceinline__ u32 f2tf(float f) {
    u32 u;
    asm("cvt.rna.tf32.f32 %0, %1;" : "=r"(u) : "f"(f));
    return u;
}
__device__ __forceinline__ void mma_tf32(float* d, const u32* a, const u32* b) {
    asm volatile(
        "mma.sync.aligned.m16n8k8.row.col.f32.tf32.tf32.f32 "
        "{%0,%1,%2,%3}, {%4,%5,%6,%7}, {%8,%9}, {%0,%1,%2,%3};"
        : "+f"(d[0]), "+f"(d[1]), "+f"(d[2]), "+f"(d[3])
        : "r"(a[0]), "r"(a[1]), "r"(a[2]), "r"(a[3]), "r"(b[0]), "r"(b[1]));
}

// ===========================================================================
// TF32 GEMM core: 128x128 tile, BK=16, 8 warps x (32x64) warp tiles.
// A,B fp32 row-major in GMEM; converted to tf32 on the smem store path.
// Epilogue selected by template tag (no device lambdas: harness nvcc
// doesn't pass --extended-lambda).
// ===========================================================================
#define SMS 132   // padded smem row stride (conflict-free fragment loads)

#define EPI_QKV  0
#define EPI_PROJ 1

template<int EPI>
__device__ __forceinline__ void gemm_tf32_body(
    const float* __restrict__ A, const float* __restrict__ Wm,
    int row0, int col0,
    float* __restrict__ dst, const float* __restrict__ bias)
{
    __shared__ u32 sA[16][SMS];
    __shared__ u32 sB[16][SMS];

    const int t    = threadIdx.x;
    const int w    = t >> 5;
    const int lane = t & 31;
    const int g    = lane >> 2;
    const int tq   = lane & 3;
    const int m0w  = (w & 3) * 32;
    const int n0w  = (w >> 2) * 64;

    const int ar = t >> 2;            // 0..63 (rows ar, ar+64)
    const int ak = (t & 3) * 4;
    const int bk = t >> 5;            // 0..7  (k rows bk, bk+8)
    const int bn = (t & 31) * 4;

    float acc[2][8][4] = {};
    float4 ra0, ra1, rb0, rb1;

    // prefetch k0=0
    ra0 = *(const float4*)&A [(row0 + ar     ) * C_ + ak];
    ra1 = *(const float4*)&A [(row0 + ar + 64) * C_ + ak];
    rb0 = *(const float4*)&Wm[(bk    ) * C_ + col0 + bn];
    rb1 = *(const float4*)&Wm[(bk + 8) * C_ + col0 + bn];

    for (int k0 = 0; k0 < C_; k0 += 16) {
        sA[ak + 0][ar]      = f2tf(ra0.x); sA[ak + 1][ar]      = f2tf(ra0.y);
        sA[ak + 2][ar]      = f2tf(ra0.z); sA[ak + 3][ar]      = f2tf(ra0.w);
        sA[ak + 0][ar + 64] = f2tf(ra1.x); sA[ak + 1][ar + 64] = f2tf(ra1.y);
        sA[ak + 2][ar + 64] = f2tf(ra1.z); sA[ak + 3][ar + 64] = f2tf(ra1.w);
        sB[bk    ][bn + 0] = f2tf(rb0.x); sB[bk    ][bn + 1] = f2tf(rb0.y);
        sB[bk    ][bn + 2] = f2tf(rb0.z); sB[bk    ][bn + 3] = f2tf(rb0.w);
        sB[bk + 8][bn + 0] = f2tf(rb1.x); sB[bk + 8][bn + 1] = f2tf(rb1.y);
        sB[bk + 8][bn + 2] = f2tf(rb1.z); sB[bk + 8][bn + 3] = f2tf(rb1.w);
        __syncthreads();

        if (k0 + 16 < C_) {
            ra0 = *(const float4*)&A [(row0 + ar     ) * C_ + k0 + 16 + ak];
            ra1 = *(const float4*)&A [(row0 + ar + 64) * C_ + k0 + 16 + ak];
            rb0 = *(const float4*)&Wm[(k0 + 16 + bk    ) * C_ + col0 + bn];
            rb1 = *(const float4*)&Wm[(k0 + 16 + bk + 8) * C_ + col0 + bn];
        }

        #pragma unroll
        for (int ks = 0; ks < 16; ks += 8) {
            u32 af[2][4], bf[8][2];
            #pragma unroll
            for (int mb = 0; mb < 2; mb++) {
                int mBase = m0w + mb * 16;
                af[mb][0] = sA[ks + tq    ][mBase + g    ];
                af[mb][1] = sA[ks + tq    ][mBase + g + 8];
                af[mb][2] = sA[ks + tq + 4][mBase + g    ];
                af[mb][3] = sA[ks + tq + 4][mBase + g + 8];
            }
            #pragma unroll
            for (int nb = 0; nb < 8; nb++) {
                int nBase = n0w + nb * 8 + g;
                bf[nb][0] = sB[ks + tq    ][nBase];
                bf[nb][1] = sB[ks + tq + 4][nBase];
            }
            #pragma unroll
            for (int mb = 0; mb < 2; mb++)
                #pragma unroll
                for (int nb = 0; nb < 8; nb++)
                    mma_tf32(acc[mb][nb], af[mb], bf[nb]);
        }
        __syncthreads();
    }

    // epilogue: reg0=(r,c) reg1=(r,c+1) reg2=(r+8,c) reg3=(r+8,c+1),
    // r = m0w+mb*16+g, c = n0w+nb*8+2*tq
    #pragma unroll
    for (int mb = 0; mb < 2; mb++) {
        int r0 = row0 + m0w + mb * 16 + g;
        #pragma unroll
        for (int nb = 0; nb < 8; nb++) {
            int c0 = col0 + n0w + nb * 8 + 2 * tq;
            #pragma unroll
            for (int rr = 0; rr < 2; rr++) {
                int row = r0 + rr * 8;
                #pragma unroll
                for (int cc = 0; cc < 2; cc++) {
                    int col = c0 + cc;
                    float v = acc[mb][nb][rr * 2 + cc];
                    if (EPI == EPI_QKV) {
                        int b  = row / N_;
                        int n  = row - b * N_;
                        int hh = col >> 6;
                        int dd = col & 63;
                        dst[(((b * H_ + hh) * N_) + n) * D_ + dd] = v;
                    } else {
                        dst[(size_t)row * C_ + col] = v + bias[col];
                    }
                }
            }
        }
    }
}

// K1: QKV GEMM (z selects Wq/Wk/Wv), scatter to head-major [B,h,N,d]
__global__ __launch_bounds__(256, 2) void qkv_mma_kernel(
    const float* __restrict__ x,
    const float* __restrict__ Wq,
    const float* __restrict__ Wk,
    const float* __restrict__ Wv)
{
    const float* W   = (blockIdx.z == 0) ? Wq : (blockIdx.z == 1) ? Wk : Wv;
    float*       dst = (blockIdx.z == 0) ? g_Q : (blockIdx.z == 1) ? g_K : g_V;
    gemm_tf32_body<EPI_QKV>(x, W, blockIdx.x * 128, blockIdx.y * 128, dst, 0);
}

// K4: projection GEMM. out = g_AO @ Wproj + bproj
__global__ __launch_bounds__(256, 2) void proj_mma_kernel(
    const float* __restrict__ Wproj,
    const float* __restrict__ bproj,
    float* __restrict__ out)
{
    gemm_tf32_body<EPI_PROJ>(g_AO, Wproj, blockIdx.x * 128, blockIdx.y * 128,
                             out, bproj);
}

// ===========================================================================
// K2: positional softmax table S_pos[h][n][m]. One warp per (h,n) row.
// ===========================================================================
__global__ __launch_bounds__(256) void pos_kernel(
    const float* __restrict__ pos_w,   // [3,12]
    const float* __restrict__ pos_b)   // [12]
{
    const int warp = threadIdx.x >> 5;
    const int lane = threadIdx.x & 31;
    const int row  = blockIdx.x * 8 + warp;
    const int h    = row / N_;
    const int n    = row - h * N_;

    const float wx = pos_w[0 * H_ + h];
    const float wy = pos_w[1 * H_ + h];
    const float wz = pos_w[2 * H_ + h];
    const float pb = pos_b[h];
    const int nx = n % GW_, ny = n / GW_;

    float buf[18];
    float mx = -1e30f;
    #pragma unroll
    for (int i = 0; i < 18; i++) {
        int m  = lane + 32 * i;
        float fdx = (float)((m % GW_) - nx);
        float fdy = (float)((m / GW_) - ny);
        float s = wx * fdx + wy * fdy + wz * (fdx * fdx + fdy * fdy) + pb;
        buf[i] = s;
        mx = fmaxf(mx, s);
    }
    #pragma unroll
    for (int o = 16; o; o >>= 1) mx = fmaxf(mx, __shfl_xor_sync(0xffffffffu, mx, o));

    float sum = 0.f;
    #pragma unroll
    for (int i = 0; i < 18; i++) { buf[i] = __expf(buf[i] - mx); sum += buf[i]; }
    #pragma unroll
    for (int o = 16; o; o >>= 1) sum += __shfl_xor_sync(0xffffffffu, sum, o);

    const float inv = 1.f / sum;
    float* dstp = g_SP + (size_t)row * N_;
    #pragma unroll
    for (int i = 0; i < 18; i++) dstp[lane + 32 * i] = buf[i] * inv;
}

// ===========================================================================
// K3: fused attention (fp32). One block = (b,h, 32 query rows), 256 threads.
// Micro-tiles are 4 rows (warp-broadcast smem reads) x 2 cols (vector reads).
// ===========================================================================
#define SQT_STRIDE 36    // [d][n], 16B aligned rows
#define SKV_STRIDE 68    // K^T [d][m] or V [m][d]
#define SS_STRIDE  580   // scores [n][m], 16B aligned rows
#define ATTN_SMEM_FLOATS (64*SQT_STRIDE + 64*SKV_STRIDE + 32*SS_STRIDE + 64)

__global__ __launch_bounds__(256) void attn_kernel(const float* __restrict__ gating)
{
    extern __shared__ __align__(16) float sm[];
    float* sQt  = sm;                              // 64 x 36
    float* sKV  = sQt + 64 * SQT_STRIDE;           // 64 x 68
    float* sS   = sKV + 64 * SKV_STRIDE;           // 32 x 580
    float* rMax = sS  + 32 * SS_STRIDE;            // [32]
    float* rInv = rMax + 32;                       // [32]

    const int b  = blockIdx.z;
    const int h  = blockIdx.y;
    const int n0 = blockIdx.x * 32;
    const int t  = threadIdx.x;
    const int tr4 = (t >> 5) * 4;   // row base: 0,4,...,28 (same for whole warp)
    const int tc2 = (t & 31) * 2;   // col base: 0..62

    const float* Qp = g_Q + (((size_t)(b * H_ + h)) * N_ + n0) * D_;
    const float* Kp = g_K + ((size_t)(b * H_ + h)) * N_ * D_;
    const float* Vp = g_V + ((size_t)(b * H_ + h)) * N_ * D_;

    // load Q tile transposed: sQt[d][n]
    for (int i = t; i < 32 * 16; i += 256) {
        int n  = i >> 4;
        int d4 = (i & 15) << 2;
        float4 v = *(const float4*)&Qp[n * D_ + d4];
        sQt[(d4 + 0) * SQT_STRIDE + n] = v.x;
        sQt[(d4 + 1) * SQT_STRIDE + n] = v.y;
        sQt[(d4 + 2) * SQT_STRIDE + n] = v.z;
        sQt[(d4 + 3) * SQT_STRIDE + n] = v.w;
    }

    // ---------------- Phase A: scores[32][576] ----------------
    for (int m0 = 0; m0 < N_; m0 += 64) {
        __syncthreads();
        for (int i = t; i < 64 * 16; i += 256) {    // K tile transposed [d][m]
            int m  = i >> 4;
            int d4 = (i & 15) << 2;
            float4 v = *(const float4*)&Kp[(m0 + m) * D_ + d4];
            sKV[(d4 + 0) * SKV_STRIDE + m] = v.x;
            sKV[(d4 + 1) * SKV_STRIDE + m] = v.y;
            sKV[(d4 + 2) * SKV_STRIDE + m] = v.z;
            sKV[(d4 + 3) * SKV_STRIDE + m] = v.w;
        }
        __syncthreads();

        float a0[4] = {}, a1[4] = {};
        #pragma unroll 16
        for (int d = 0; d < 64; d++) {
            float4 q  = *(float4*)&sQt[d * SQT_STRIDE + tr4];   // warp broadcast
            float2 kv = *(float2*)&sKV[d * SKV_STRIDE + tc2];
            a0[0] += q.x * kv.x; a1[0] += q.x * kv.y;
            a0[1] += q.y * kv.x; a1[1] += q.y * kv.y;
            a0[2] += q.z * kv.x; a1[2] += q.z * kv.y;
            a0[3] += q.w * kv.x; a1[3] += q.w * kv.y;
        }
        #pragma unroll
        for (int i = 0; i < 4; i++) {
            float2 s; s.x = a0[i] * 0.125f; s.y = a1[i] * 0.125f;
            *(float2*)&sS[(tr4 + i) * SS_STRIDE + m0 + tc2] = s;
        }
    }
    __syncthreads();

    // ---------------- Phase B: row max & sumexp ----------------
    {
        const int warp = t >> 5, lane = t & 31;
        for (int r = warp; r < 32; r += 8) {
            const float* rowp = sS + r * SS_STRIDE;
            float mx = -1e30f;
            #pragma unroll
            for (int i = 0; i < 18; i++) mx = fmaxf(mx, rowp[lane + 32 * i]);
            #pragma unroll
            for (int o = 16; o; o >>= 1) mx = fmaxf(mx, __shfl_xor_sync(0xffffffffu, mx, o));
            float sum = 0.f;
            #pragma unroll
            for (int i = 0; i < 18; i++) sum += __expf(rowp[lane + 32 * i] - mx);
            #pragma unroll
            for (int o = 16; o; o >>= 1) sum += __shfl_xor_sync(0xffffffffu, sum, o);
            if (lane == 0) { rMax[r] = mx; rInv[r] = 1.f / sum; }
        }
    }
    __syncthreads();

    // ---------------- Phase C: combine with positional ----------------
    {
        const float gt = 1.f / (1.f + __expf(-gating[h]));
        const float c1 = 1.f - gt;
        const float* SP = g_SP + ((size_t)h * N_ + n0) * N_;
        for (int j = t; j < 32 * N_; j += 256) {
            int n = j / N_;
            int m = j - n * N_;
            float p = __expf(sS[n * SS_STRIDE + m] - rMax[n]) * rInv[n];
            sS[n * SS_STRIDE + m] = c1 * p + gt * SP[n * N_ + m];
        }
    }

    // ---------------- Phase D: out[32][64] = w @ V ----------------
    float o0[4] = {}, o1[4] = {};
    for (int m0 = 0; m0 < N_; m0 += 64) {
        __syncthreads();
        for (int i = t; i < 64 * 16; i += 256) {    // V tile [m][d]
            int m  = i >> 4;
            int d4 = (i & 15) << 2;
            *(float4*)&sKV[m * SKV_STRIDE + d4] = *(const float4*)&Vp[(m0 + m) * D_ + d4];
        }
        __syncthreads();

        #pragma unroll 16
        for (int m = 0; m < 64; m++) {
            float w0 = sS[(tr4 + 0) * SS_STRIDE + m0 + m];  // broadcast
            float w1 = sS[(tr4 + 1) * SS_STRIDE + m0 + m];
            float w2 = sS[(tr4 + 2) * SS_STRIDE + m0 + m];
            float w3 = sS[(tr4 + 3) * SS_STRIDE + m0 + m];
            float2 v = *(float2*)&sKV[m * SKV_STRIDE + tc2];
            o0[0] += w0 * v.x; o1[0] += w0 * v.y;
            o0[1] += w1 * v.x; o1[1] += w1 * v.y;
            o0[2] += w2 * v.x; o1[2] += w2 * v.y;
            o0[3] += w3 * v.x; o1[3] += w3 * v.y;
        }
    }

    float* Op = g_AO + ((size_t)(b * N_ + n0)) * C_ + h * D_;
    #pragma unroll
    for (int i = 0; i < 4; i++) {
        float2 v; v.x = o0[i]; v.y = o1[i];
        *(float2*)&Op[(tr4 + i) * C_ + tc2] = v;
    }
}

// ===========================================================================
extern "C" void kernel_launch(void* const* d_in, const int* in_sizes, int n_in,
                              void* d_out, int out_size)
{
    const float* x      = (const float*)d_in[0];
    const float* Wq     = (const float*)d_in[1];
    const float* Wk     = (const float*)d_in[2];
    const float* Wv     = (const float*)d_in[3];
    const float* Wproj  = (const float*)d_in[4];
    const float* bproj  = (const float*)d_in[5];
    const float* pos_w  = (const float*)d_in[6];
    const float* pos_b  = (const float*)d_in[7];
    const float* gating = (const float*)d_in[8];
    float* out = (float*)d_out;

    const size_t attn_smem = ATTN_SMEM_FLOATS * sizeof(float);   // ~101 KB
    cudaFuncSetAttribute(attn_kernel, cudaFuncAttributeMaxDynamicSharedMemorySize,
                         (int)attn_smem);

    qkv_mma_kernel<<<dim3(B_ * N_ / 128, C_ / 128, 3), 256>>>(x, Wq, Wk, Wv);
    pos_kernel<<<(H_ * N_) / 8, 256>>>(pos_w, pos_b);
    attn_kernel<<<dim3(N_ / 32, H_, B_), 256, attn_smem>>>(gating);
    proj_mma_kernel<<<dim3(B_ * N_ / 128, C_ / 128), 256>>>(Wproj, bproj, out);
}

// round 8
// speedup vs baseline: 1.8182x; 1.1104x over previous
#include <cuda_runtime.h>

typedef unsigned int u32;

// Problem constants (fixed by the dataset)
#define B_  16
#define H_  12
#define N_  576
#define D_  64
#define C_  768
#define GW_ 24

// ---- scratch ----
__device__ float g_Q [B_*H_*N_*D_];
__device__ float g_K [B_*H_*N_*D_];
__device__ float g_V [B_*H_*N_*D_];
__device__ float g_AO[B_*N_*C_];
__device__ float g_SP[H_*N_*N_];      // positional softmax table (L2-resident, 15.9MB)

// ---------------------------------------------------------------------------
// TF32 helpers
// ---------------------------------------------------------------------------
__device__ __forceinline__ u32 f2tf(float f) {
    u32 u;
    asm("cvt.rna.tf32.f32 %0, %1;" : "=r"(u) : "f"(f));
    return u;
}
// Fragment mapping (verified by passing GEMM):
//   A: a0=(m=g,k=tq) a1=(m=g+8,k=tq) a2=(m=g,k=tq+4) a3=(m=g+8,k=tq+4)
//   B: b0=(k=tq,n=g) b1=(k=tq+4,n=g)
//   C: c0=(m=g,n=2tq) c1=(g,2tq+1) c2=(g+8,2tq) c3=(g+8,2tq+1)
__device__ __forceinline__ void mma_tf32(float* d, const u32* a, const u32* b) {
    asm volatile(
        "mma.sync.aligned.m16n8k8.row.col.f32.tf32.tf32.f32 "
        "{%0,%1,%2,%3}, {%4,%5,%6,%7}, {%8,%9}, {%0,%1,%2,%3};"
        : "+f"(d[0]), "+f"(d[1]), "+f"(d[2]), "+f"(d[3])
        : "r"(a[0]), "r"(a[1]), "r"(a[2]), "r"(a[3]), "r"(b[0]), "r"(b[1]));
}

// ===========================================================================
// TF32 GEMM core: 128x128 tile, BK=16, 8 warps x (32x64) warp tiles.
// ===========================================================================
#define SMS 132

#define EPI_QKV  0
#define EPI_PROJ 1

template<int EPI>
__device__ __forceinline__ void gemm_tf32_body(
    const float* __restrict__ A, const float* __restrict__ Wm,
    int row0, int col0,
    float* __restrict__ dst, const float* __restrict__ bias)
{
    __shared__ u32 sA[16][SMS];
    __shared__ u32 sB[16][SMS];

    const int t    = threadIdx.x;
    const int w    = t >> 5;
    const int lane = t & 31;
    const int g    = lane >> 2;
    const int tq   = lane & 3;
    const int m0w  = (w & 3) * 32;
    const int n0w  = (w >> 2) * 64;

    const int ar = t >> 2;
    const int ak = (t & 3) * 4;
    const int bk = t >> 5;
    const int bn = (t & 31) * 4;

    float acc[2][8][4] = {};
    float4 ra0, ra1, rb0, rb1;

    ra0 = *(const float4*)&A [(row0 + ar     ) * C_ + ak];
    ra1 = *(const float4*)&A [(row0 + ar + 64) * C_ + ak];
    rb0 = *(const float4*)&Wm[(bk    ) * C_ + col0 + bn];
    rb1 = *(const float4*)&Wm[(bk + 8) * C_ + col0 + bn];

    for (int k0 = 0; k0 < C_; k0 += 16) {
        sA[ak + 0][ar]      = f2tf(ra0.x); sA[ak + 1][ar]      = f2tf(ra0.y);
        sA[ak + 2][ar]      = f2tf(ra0.z); sA[ak + 3][ar]      = f2tf(ra0.w);
        sA[ak + 0][ar + 64] = f2tf(ra1.x); sA[ak + 1][ar + 64] = f2tf(ra1.y);
        sA[ak + 2][ar + 64] = f2tf(ra1.z); sA[ak + 3][ar + 64] = f2tf(ra1.w);
        sB[bk    ][bn + 0] = f2tf(rb0.x); sB[bk    ][bn + 1] = f2tf(rb0.y);
        sB[bk    ][bn + 2] = f2tf(rb0.z); sB[bk    ][bn + 3] = f2tf(rb0.w);
        sB[bk + 8][bn + 0] = f2tf(rb1.x); sB[bk + 8][bn + 1] = f2tf(rb1.y);
        sB[bk + 8][bn + 2] = f2tf(rb1.z); sB[bk + 8][bn + 3] = f2tf(rb1.w);
        __syncthreads();

        if (k0 + 16 < C_) {
            ra0 = *(const float4*)&A [(row0 + ar     ) * C_ + k0 + 16 + ak];
            ra1 = *(const float4*)&A [(row0 + ar + 64) * C_ + k0 + 16 + ak];
            rb0 = *(const float4*)&Wm[(k0 + 16 + bk    ) * C_ + col0 + bn];
            rb1 = *(const float4*)&Wm[(k0 + 16 + bk + 8) * C_ + col0 + bn];
        }

        #pragma unroll
        for (int ks = 0; ks < 16; ks += 8) {
            u32 af[2][4], bf[8][2];
            #pragma unroll
            for (int mb = 0; mb < 2; mb++) {
                int mBase = m0w + mb * 16;
                af[mb][0] = sA[ks + tq    ][mBase + g    ];
                af[mb][1] = sA[ks + tq    ][mBase + g + 8];
                af[mb][2] = sA[ks + tq + 4][mBase + g    ];
                af[mb][3] = sA[ks + tq + 4][mBase + g + 8];
            }
            #pragma unroll
            for (int nb = 0; nb < 8; nb++) {
                int nBase = n0w + nb * 8 + g;
                bf[nb][0] = sB[ks + tq    ][nBase];
                bf[nb][1] = sB[ks + tq + 4][nBase];
            }
            #pragma unroll
            for (int mb = 0; mb < 2; mb++)
                #pragma unroll
                for (int nb = 0; nb < 8; nb++)
                    mma_tf32(acc[mb][nb], af[mb], bf[nb]);
        }
        __syncthreads();
    }

    #pragma unroll
    for (int mb = 0; mb < 2; mb++) {
        int r0 = row0 + m0w + mb * 16 + g;
        #pragma unroll
        for (int nb = 0; nb < 8; nb++) {
            int c0 = col0 + n0w + nb * 8 + 2 * tq;
            #pragma unroll
            for (int rr = 0; rr < 2; rr++) {
                int row = r0 + rr * 8;
                #pragma unroll
                for (int cc = 0; cc < 2; cc++) {
                    int col = c0 + cc;
                    float v = acc[mb][nb][rr * 2 + cc];
                    if (EPI == EPI_QKV) {
                        int b  = row / N_;
                        int n  = row - b * N_;
                        int hh = col >> 6;
                        int dd = col & 63;
                        dst[(((b * H_ + hh) * N_) + n) * D_ + dd] = v;
                    } else {
                        dst[(size_t)row * C_ + col] = v + bias[col];
                    }
                }
            }
        }
    }
}

__global__ __launch_bounds__(256, 2) void qkv_mma_kernel(
    const float* __restrict__ x,
    const float* __restrict__ Wq,
    const float* __restrict__ Wk,
    const float* __restrict__ Wv)
{
    const float* W   = (blockIdx.z == 0) ? Wq : (blockIdx.z == 1) ? Wk : Wv;
    float*       dst = (blockIdx.z == 0) ? g_Q : (blockIdx.z == 1) ? g_K : g_V;
    gemm_tf32_body<EPI_QKV>(x, W, blockIdx.x * 128, blockIdx.y * 128, dst, 0);
}

__global__ __launch_bounds__(256, 2) void proj_mma_kernel(
    const float* __restrict__ Wproj,
    const float* __restrict__ bproj,
    float* __restrict__ out)
{
    gemm_tf32_body<EPI_PROJ>(g_AO, Wproj, blockIdx.x * 128, blockIdx.y * 128,
                             out, bproj);
}

// ===========================================================================
// K2: positional softmax table S_pos[h][n][m]. One warp per (h,n) row.
// ===========================================================================
__global__ __launch_bounds__(256) void pos_kernel(
    const float* __restrict__ pos_w,
    const float* __restrict__ pos_b)
{
    const int warp = threadIdx.x >> 5;
    const int lane = threadIdx.x & 31;
    const int row  = blockIdx.x * 8 + warp;
    const int h    = row / N_;
    const int n    = row - h * N_;

    const float wx = pos_w[0 * H_ + h];
    const float wy = pos_w[1 * H_ + h];
    const float wz = pos_w[2 * H_ + h];
    const float pb = pos_b[h];
    const int nx = n % GW_, ny = n / GW_;

    float buf[18];
    float mx = -1e30f;
    #pragma unroll
    for (int i = 0; i < 18; i++) {
        int m  = lane + 32 * i;
        float fdx = (float)((m % GW_) - nx);
        float fdy = (float)((m / GW_) - ny);
        float s = wx * fdx + wy * fdy + wz * (fdx * fdx + fdy * fdy) + pb;
        buf[i] = s;
        mx = fmaxf(mx, s);
    }
    #pragma unroll
    for (int o = 16; o; o >>= 1) mx = fmaxf(mx, __shfl_xor_sync(0xffffffffu, mx, o));

    float sum = 0.f;
    #pragma unroll
    for (int i = 0; i < 18; i++) { buf[i] = __expf(buf[i] - mx); sum += buf[i]; }
    #pragma unroll
    for (int o = 16; o; o >>= 1) sum += __shfl_xor_sync(0xffffffffu, sum, o);

    const float inv = 1.f / sum;
    float* dstp = g_SP + (size_t)row * N_;
    #pragma unroll
    for (int i = 0; i < 18; i++) dstp[lane + 32 * i] = buf[i] * inv;
}

// ===========================================================================
// K3: fused attention with TF32 MMA for both GEMM phases.
// One block = (b, h, 32 query rows), 256 threads = 8 warps.
// Warp w: row-half = (w&1)*16, col-group = (w>>2? no, w>>1)*16 within 64-wide tiles.
//   Phase A: scores[32][576] = Q(32x64) @ K^T, 9 key tiles of 64.
//   Phase B: row max/sumexp. Phase C: blend with positional table.
//   Phase D: out[32][64] = W(32x576) @ V, streaming V in 9 tiles of 64.
// SMEM strides chosen so every fragment LDS is 32-bank conflict-free:
//   sQ/sK stride 68 (4g+tq), sV stride 72 (8tq+g), sS stride 580 (4g+tq).
// ===========================================================================
#define SQ_ST 68
#define SK_ST 68
#define SV_ST 72
#define SS_ST 580
#define ATTN_SMEM_WORDS (32*SQ_ST + 64*SV_ST + 32*SS_ST + 64)

__global__ __launch_bounds__(256) void attn_kernel(const float* __restrict__ gating)
{
    extern __shared__ __align__(16) u32 smw[];
    u32*   sQ   = smw;                      // tf32 [32][SQ_ST]
    u32*   sKV  = sQ + 32 * SQ_ST;          // tf32 K [64][SK_ST] / V [64][SV_ST]
    float* sS   = (float*)(sKV + 64 * SV_ST); // fp32 [32][SS_ST]
    float* rMax = sS + 32 * SS_ST;          // [32]
    float* rInv = rMax + 32;                // [32]

    const int b  = blockIdx.z;
    const int h  = blockIdx.y;
    const int n0 = blockIdx.x * 32;
    const int t  = threadIdx.x;
    const int w    = t >> 5;
    const int lane = t & 31;
    const int g    = lane >> 2;
    const int tq   = lane & 3;
    const int roff = (w & 1) * 16;     // 0 or 16: row half
    const int cg   = (w >> 1) * 16;    // 0,16,32,48: col group within 64

    const float* Qp = g_Q + (((size_t)(b * H_ + h)) * N_ + n0) * D_;
    const float* Kp = g_K + ((size_t)(b * H_ + h)) * N_ * D_;
    const float* Vp = g_V + ((size_t)(b * H_ + h)) * N_ * D_;

    // load Q tile (tf32) into sQ[m][d]
    for (int i = t; i < 32 * 16; i += 256) {
        int n  = i >> 4;
        int d4 = (i & 15) << 2;
        float4 v = *(const float4*)&Qp[n * D_ + d4];
        u32* p = &sQ[n * SQ_ST + d4];
        p[0] = f2tf(v.x); p[1] = f2tf(v.y); p[2] = f2tf(v.z); p[3] = f2tf(v.w);
    }

    // ---------------- Phase A: scores via MMA ----------------
    for (int m0 = 0; m0 < N_; m0 += 64) {
        __syncthreads();
        #pragma unroll
        for (int it = 0; it < 4; it++) {          // K tile [64][64] -> sK[m][d] tf32
            int idx = t + 256 * it;
            int m  = idx >> 4;
            int d4 = (idx & 15) << 2;
            float4 v = *(const float4*)&Kp[(m0 + m) * D_ + d4];
            u32* p = &sKV[m * SK_ST + d4];
            p[0] = f2tf(v.x); p[1] = f2tf(v.y); p[2] = f2tf(v.z); p[3] = f2tf(v.w);
        }
        __syncthreads();

        float acc[2][4] = {};
        #pragma unroll
        for (int ks = 0; ks < 8; ks++) {
            int k0 = ks * 8;
            u32 a[4];
            a[0] = sQ[(roff + g    ) * SQ_ST + k0 + tq    ];
            a[1] = sQ[(roff + g + 8) * SQ_ST + k0 + tq    ];
            a[2] = sQ[(roff + g    ) * SQ_ST + k0 + tq + 4];
            a[3] = sQ[(roff + g + 8) * SQ_ST + k0 + tq + 4];
            #pragma unroll
            for (int nt = 0; nt < 2; nt++) {
                int nb = cg + nt * 8;
                u32 bfr[2];
                bfr[0] = sKV[(nb + g) * SK_ST + k0 + tq    ];
                bfr[1] = sKV[(nb + g) * SK_ST + k0 + tq + 4];
                mma_tf32(acc[nt], a, bfr);
            }
        }
        #pragma unroll
        for (int nt = 0; nt < 2; nt++) {
            int c0 = m0 + cg + nt * 8 + 2 * tq;
            float2 v0; v0.x = acc[nt][0] * 0.125f; v0.y = acc[nt][1] * 0.125f;
            float2 v1; v1.x = acc[nt][2] * 0.125f; v1.y = acc[nt][3] * 0.125f;
            *(float2*)&sS[(roff + g    ) * SS_ST + c0] = v0;
            *(float2*)&sS[(roff + g + 8) * SS_ST + c0] = v1;
        }
    }
    __syncthreads();

    // ---------------- Phase B: row max & sumexp ----------------
    {
        for (int r = w; r < 32; r += 8) {
            const float* rowp = sS + r * SS_ST;
            float mx = -1e30f;
            #pragma unroll
            for (int i = 0; i < 18; i++) mx = fmaxf(mx, rowp[lane + 32 * i]);
            #pragma unroll
            for (int o = 16; o; o >>= 1) mx = fmaxf(mx, __shfl_xor_sync(0xffffffffu, mx, o));
            float sum = 0.f;
            #pragma unroll
            for (int i = 0; i < 18; i++) sum += __expf(rowp[lane + 32 * i] - mx);
            #pragma unroll
            for (int o = 16; o; o >>= 1) sum += __shfl_xor_sync(0xffffffffu, sum, o);
            if (lane == 0) { rMax[r] = mx; rInv[r] = 1.f / sum; }
        }
    }
    __syncthreads();

    // ---------------- Phase C: softmax + blend with positional ----------------
    {
        const float gt = 1.f / (1.f + __expf(-gating[h]));
        const float c1 = 1.f - gt;
        const float* SP = g_SP + ((size_t)h * N_ + n0) * N_;
        #pragma unroll
        for (int it = 0; it < 72; it++) {         // 32*576/256
            int j = t + 256 * it;
            int n = j / N_;
            int m = j - n * N_;
            float p = __expf(sS[n * SS_ST + m] - rMax[n]) * rInv[n];
            sS[n * SS_ST + m] = c1 * p + gt * SP[n * N_ + m];
        }
    }

    // ---------------- Phase D: out = W @ V via MMA ----------------
    float accD[2][4] = {};
    for (int m0 = 0; m0 < N_; m0 += 64) {
        __syncthreads();
        #pragma unroll
        for (int it = 0; it < 4; it++) {          // V tile [64][64] -> sV[m][d] tf32
            int idx = t + 256 * it;
            int m  = idx >> 4;
            int d4 = (idx & 15) << 2;
            float4 v = *(const float4*)&Vp[(m0 + m) * D_ + d4];
            u32* p = &sKV[m * SV_ST + d4];
            p[0] = f2tf(v.x); p[1] = f2tf(v.y); p[2] = f2tf(v.z); p[3] = f2tf(v.w);
        }
        __syncthreads();

        #pragma unroll
        for (int ks = 0; ks < 8; ks++) {
            int k0 = m0 + ks * 8;
            u32 a[4];
            a[0] = f2tf(sS[(roff + g    ) * SS_ST + k0 + tq    ]);
            a[1] = f2tf(sS[(roff + g + 8) * SS_ST + k0 + tq    ]);
            a[2] = f2tf(sS[(roff + g    ) * SS_ST + k0 + tq + 4]);
            a[3] = f2tf(sS[(roff + g + 8) * SS_ST + k0 + tq + 4]);
            #pragma unroll
            for (int nt = 0; nt < 2; nt++) {
                int nb = cg + nt * 8;
                u32 bfr[2];
                bfr[0] = sKV[(ks * 8 + tq    ) * SV_ST + nb + g];
                bfr[1] = sKV[(ks * 8 + tq + 4) * SV_ST + nb + g];
                mma_tf32(accD[nt], a, bfr);
            }
        }
    }

    float* Op = g_AO + ((size_t)(b * N_ + n0)) * C_ + h * D_;
    #pragma unroll
    for (int nt = 0; nt < 2; nt++) {
        int c0 = cg + nt * 8 + 2 * tq;
        float2 v0; v0.x = accD[nt][0]; v0.y = accD[nt][1];
        float2 v1; v1.x = accD[nt][2]; v1.y = accD[nt][3];
        *(float2*)&Op[(roff + g    ) * C_ + c0] = v0;
        *(float2*)&Op[(roff + g + 8) * C_ + c0] = v1;
    }
}

// ===========================================================================
extern "C" void kernel_launch(void* const* d_in, const int* in_sizes, int n_in,
                              void* d_out, int out_size)
{
    const float* x      = (const float*)d_in[0];
    const float* Wq     = (const float*)d_in[1];
    const float* Wk     = (const float*)d_in[2];
    const float* Wv     = (const float*)d_in[3];
    const float* Wproj  = (const float*)d_in[4];
    const float* bproj  = (const float*)d_in[5];
    const float* pos_w  = (const float*)d_in[6];
    const float* pos_b  = (const float*)d_in[7];
    const float* gating = (const float*)d_in[8];
    float* out = (float*)d_out;

    const size_t attn_smem = ATTN_SMEM_WORDS * sizeof(u32);   // ~101 KB
    cudaFuncSetAttribute(attn_kernel, cudaFuncAttributeMaxDynamicSharedMemorySize,
                         (int)attn_smem);

    qkv_mma_kernel<<<dim3(B_ * N_ / 128, C_ / 128, 3), 256>>>(x, Wq, Wk, Wv);
    pos_kernel<<<(H_ * N_) / 8, 256>>>(pos_w, pos_b);
    attn_kernel<<<dim3(N_ / 32, H_, B_), 256, attn_smem>>>(gating);
    proj_mma_kernel<<<dim3(B_ * N_ / 128, C_ / 128), 256>>>(Wproj, bproj, out);
}

// round 9
// speedup vs baseline: 3.4453x; 1.8949x over previous
#include <cuda_runtime.h>

typedef unsigned int u32;

// Problem constants (fixed by the dataset)
#define B_  16
#define H_  12
#define N_  576
#define D_  64
#define C_  768
#define GW_ 24

// ---- scratch ----
__device__ float g_Q [B_*H_*N_*D_];
__device__ float g_K [B_*H_*N_*D_];
__device__ float g_V [B_*H_*N_*D_];
__device__ float g_AO[B_*N_*C_];
__device__ float g_SP[H_*N_*N_];      // positional softmax table (L2-resident, 15.9MB)

// ---------------------------------------------------------------------------
// TF32 helpers
// ---------------------------------------------------------------------------
__device__ __forceinline__ u32 f2tf(float f) {
    u32 u;
    asm("cvt.rna.tf32.f32 %0, %1;" : "=r"(u) : "f"(f));
    return u;
}
// Fragment mapping (m16n8k8, verified):
//   A: a0=(m=g,k=tq) a1=(m=g+8,k=tq) a2=(m=g,k=tq+4) a3=(m=g+8,k=tq+4)
//   B: b0=(k=tq,n=g) b1=(k=tq+4,n=g)
//   C: c0=(m=g,n=2tq) c1=(g,2tq+1) c2=(g+8,2tq) c3=(g+8,2tq+1)
__device__ __forceinline__ void mma_tf32(float* d, const u32* a, const u32* b) {
    asm volatile(
        "mma.sync.aligned.m16n8k8.row.col.f32.tf32.tf32.f32 "
        "{%0,%1,%2,%3}, {%4,%5,%6,%7}, {%8,%9}, {%0,%1,%2,%3};"
        : "+f"(d[0]), "+f"(d[1]), "+f"(d[2]), "+f"(d[3])
        : "r"(a[0]), "r"(a[1]), "r"(a[2]), "r"(a[3]), "r"(b[0]), "r"(b[1]));
}

__device__ __forceinline__ uint4 f2tf4(float4 v) {
    uint4 u; u.x = f2tf(v.x); u.y = f2tf(v.y); u.z = f2tf(v.z); u.w = f2tf(v.w);
    return u;
}

// ===========================================================================
// TF32 GEMM core: 128x128 tile, BK=16, 8 warps x (32x64) warp tiles.
// Conflict-free layouts:
//   sA [m=128][SA_ST=68]: frag banks = 4g+tq (+0/8) -> 32 distinct.
//   sB [k=16][SB_ST=136]: frag banks = 8tq+g       -> 32 distinct.
// uint4 smem stores (B stores conflict-free; A ~2-way).
// ===========================================================================
#define SA_ST 68
#define SB_ST 136

#define EPI_QKV  0
#define EPI_PROJ 1

template<int EPI>
__device__ __forceinline__ void gemm_tf32_body(
    const float* __restrict__ A, const float* __restrict__ Wm,
    int row0, int col0,
    float* __restrict__ dst, const float* __restrict__ bias)
{
    __shared__ u32 sA[128 * SA_ST];
    __shared__ u32 sB[16 * SB_ST];

    const int t    = threadIdx.x;
    const int w    = t >> 5;
    const int lane = t & 31;
    const int g    = lane >> 2;
    const int tq   = lane & 3;
    const int m0w  = (w & 3) * 32;
    const int n0w  = (w >> 2) * 64;

    const int ar = t >> 2;            // 0..63 (rows ar, ar+64)
    const int ak = (t & 3) * 4;       // 0,4,8,12
    const int bk = t >> 5;            // 0..7  (k rows bk, bk+8)
    const int bn = (t & 31) * 4;

    float acc[2][8][4] = {};
    float4 ra0, ra1, rb0, rb1;

    ra0 = *(const float4*)&A [(row0 + ar     ) * C_ + ak];
    ra1 = *(const float4*)&A [(row0 + ar + 64) * C_ + ak];
    rb0 = *(const float4*)&Wm[(bk    ) * C_ + col0 + bn];
    rb1 = *(const float4*)&Wm[(bk + 8) * C_ + col0 + bn];

    for (int k0 = 0; k0 < C_; k0 += 16) {
        *(uint4*)&sA[(ar     ) * SA_ST + ak] = f2tf4(ra0);
        *(uint4*)&sA[(ar + 64) * SA_ST + ak] = f2tf4(ra1);
        *(uint4*)&sB[(bk     ) * SB_ST + bn] = f2tf4(rb0);
        *(uint4*)&sB[(bk + 8 ) * SB_ST + bn] = f2tf4(rb1);
        __syncthreads();

        if (k0 + 16 < C_) {
            ra0 = *(const float4*)&A [(row0 + ar     ) * C_ + k0 + 16 + ak];
            ra1 = *(const float4*)&A [(row0 + ar + 64) * C_ + k0 + 16 + ak];
            rb0 = *(const float4*)&Wm[(k0 + 16 + bk    ) * C_ + col0 + bn];
            rb1 = *(const float4*)&Wm[(k0 + 16 + bk + 8) * C_ + col0 + bn];
        }

        #pragma unroll
        for (int ks = 0; ks < 16; ks += 8) {
            u32 af[2][4], bf[8][2];
            #pragma unroll
            for (int mb = 0; mb < 2; mb++) {
                int mrow = m0w + mb * 16 + g;
                af[mb][0] = sA[(mrow    ) * SA_ST + ks + tq    ];
                af[mb][1] = sA[(mrow + 8) * SA_ST + ks + tq    ];
                af[mb][2] = sA[(mrow    ) * SA_ST + ks + tq + 4];
                af[mb][3] = sA[(mrow + 8) * SA_ST + ks + tq + 4];
            }
            #pragma unroll
            for (int nb = 0; nb < 8; nb++) {
                int nc = n0w + nb * 8 + g;
                bf[nb][0] = sB[(ks + tq    ) * SB_ST + nc];
                bf[nb][1] = sB[(ks + tq + 4) * SB_ST + nc];
            }
            #pragma unroll
            for (int mb = 0; mb < 2; mb++)
                #pragma unroll
                for (int nb = 0; nb < 8; nb++)
                    mma_tf32(acc[mb][nb], af[mb], bf[nb]);
        }
        __syncthreads();
    }

    // epilogue: float2 stores (cols 2tq, 2tq+1 are adjacent)
    #pragma unroll
    for (int mb = 0; mb < 2; mb++) {
        int r0 = row0 + m0w + mb * 16 + g;
        #pragma unroll
        for (int nb = 0; nb < 8; nb++) {
            int c0 = col0 + n0w + nb * 8 + 2 * tq;
            #pragma unroll
            for (int rr = 0; rr < 2; rr++) {
                int row = r0 + rr * 8;
                float2 v;
                v.x = acc[mb][nb][rr * 2 + 0];
                v.y = acc[mb][nb][rr * 2 + 1];
                if (EPI == EPI_QKV) {
                    int b  = row / N_;
                    int n  = row - b * N_;
                    int hh = c0 >> 6;
                    int dd = c0 & 63;       // even, dd+1 in same head
                    *(float2*)&dst[(((b * H_ + hh) * N_) + n) * D_ + dd] = v;
                } else {
                    v.x += bias[c0];
                    v.y += bias[c0 + 1];
                    *(float2*)&dst[(size_t)row * C_ + c0] = v;
                }
            }
        }
    }
}

__global__ __launch_bounds__(256, 2) void qkv_mma_kernel(
    const float* __restrict__ x,
    const float* __restrict__ Wq,
    const float* __restrict__ Wk,
    const float* __restrict__ Wv)
{
    const float* W   = (blockIdx.z == 0) ? Wq : (blockIdx.z == 1) ? Wk : Wv;
    float*       dst = (blockIdx.z == 0) ? g_Q : (blockIdx.z == 1) ? g_K : g_V;
    gemm_tf32_body<EPI_QKV>(x, W, blockIdx.x * 128, blockIdx.y * 128, dst, 0);
}

__global__ __launch_bounds__(256, 2) void proj_mma_kernel(
    const float* __restrict__ Wproj,
    const float* __restrict__ bproj,
    float* __restrict__ out)
{
    gemm_tf32_body<EPI_PROJ>(g_AO, Wproj, blockIdx.x * 128, blockIdx.y * 128,
                             out, bproj);
}

// ===========================================================================
// K2: positional softmax table S_pos[h][n][m]. One warp per (h,n) row.
// ===========================================================================
__global__ __launch_bounds__(256) void pos_kernel(
    const float* __restrict__ pos_w,
    const float* __restrict__ pos_b)
{
    const int warp = threadIdx.x >> 5;
    const int lane = threadIdx.x & 31;
    const int row  = blockIdx.x * 8 + warp;
    const int h    = row / N_;
    const int n    = row - h * N_;

    const float wx = pos_w[0 * H_ + h];
    const float wy = pos_w[1 * H_ + h];
    const float wz = pos_w[2 * H_ + h];
    const float pb = pos_b[h];
    const int nx = n % GW_, ny = n / GW_;

    float buf[18];
    float mx = -1e30f;
    #pragma unroll
    for (int i = 0; i < 18; i++) {
        int m  = lane + 32 * i;
        float fdx = (float)((m % GW_) - nx);
        float fdy = (float)((m / GW_) - ny);
        float s = wx * fdx + wy * fdy + wz * (fdx * fdx + fdy * fdy) + pb;
        buf[i] = s;
        mx = fmaxf(mx, s);
    }
    #pragma unroll
    for (int o = 16; o; o >>= 1) mx = fmaxf(mx, __shfl_xor_sync(0xffffffffu, mx, o));

    float sum = 0.f;
    #pragma unroll
    for (int i = 0; i < 18; i++) { buf[i] = __expf(buf[i] - mx); sum += buf[i]; }
    #pragma unroll
    for (int o = 16; o; o >>= 1) sum += __shfl_xor_sync(0xffffffffu, sum, o);

    const float inv = 1.f / sum;
    float* dstp = g_SP + (size_t)row * N_;
    #pragma unroll
    for (int i = 0; i < 18; i++) dstp[lane + 32 * i] = buf[i] * inv;
}

// ===========================================================================
// K3: fused attention, TF32 MMA.
//  - Q fragments hoisted to registers (loop-invariant over the 9 K tiles).
//  - Register-prefetch of next K/V tile (LDG overlaps MMA).
//  - Merged softmax+blend: scores held in registers, single exp, float4.
// Bank-verified strides: sQ/sK 68 (phase A: banks 4g+tq CF),
//                        sV 72  (phase D: banks 8tq+g CF),
//                        sS 580 (phase D A-frag CF).
// ===========================================================================
#define SQ_ST 68
#define SK_ST 68
#define SV_ST 72
#define SS_ST 580
#define ATTN_SMEM_WORDS (32*SQ_ST + 64*SV_ST + 32*SS_ST)

__global__ __launch_bounds__(256, 2) void attn_kernel(const float* __restrict__ gating)
{
    extern __shared__ __align__(16) u32 smw[];
    u32*   sQ   = smw;                        // tf32 [32][SQ_ST]
    u32*   sKV  = sQ + 32 * SQ_ST;            // tf32 K [64][SK_ST] / V [64][SV_ST]
    float* sS   = (float*)(sKV + 64 * SV_ST); // fp32 [32][SS_ST]

    const int b  = blockIdx.z;
    const int h  = blockIdx.y;
    const int n0 = blockIdx.x * 32;
    const int t  = threadIdx.x;
    const int w    = t >> 5;
    const int lane = t & 31;
    const int g    = lane >> 2;
    const int tq   = lane & 3;
    const int roff = (w & 1) * 16;     // row half
    const int cg   = (w >> 1) * 16;    // col group within 64

    const float* Qp = g_Q + (((size_t)(b * H_ + h)) * N_ + n0) * D_;
    const float* Kp = g_K + ((size_t)(b * H_ + h)) * N_ * D_;
    const float* Vp = g_V + ((size_t)(b * H_ + h)) * N_ * D_;

    // tile-loader index map (64x64 tile, 4 float4 per thread)
    const int lm[4] = { (t + 0) >> 4, (t + 256) >> 4, (t + 512) >> 4, (t + 768) >> 4 };
    const int ld4   = (t & 15) << 2;

    // load Q tile (tf32) into sQ[m][d]
    for (int i = t; i < 32 * 16; i += 256) {
        int n  = i >> 4;
        int d4 = (i & 15) << 2;
        *(uint4*)&sQ[n * SQ_ST + d4] = f2tf4(*(const float4*)&Qp[n * D_ + d4]);
    }
    __syncthreads();

    // hoist Q fragments (invariant across K tiles)
    u32 qf[8][4];
    #pragma unroll
    for (int ks = 0; ks < 8; ks++) {
        int k0 = ks * 8;
        qf[ks][0] = sQ[(roff + g    ) * SQ_ST + k0 + tq    ];
        qf[ks][1] = sQ[(roff + g + 8) * SQ_ST + k0 + tq    ];
        qf[ks][2] = sQ[(roff + g    ) * SQ_ST + k0 + tq + 4];
        qf[ks][3] = sQ[(roff + g + 8) * SQ_ST + k0 + tq + 4];
    }

    // ---------------- Phase A: scores via MMA (prefetched tiles) -----------
    float4 pre[4];
    #pragma unroll
    for (int it = 0; it < 4; it++)
        pre[it] = *(const float4*)&Kp[lm[it] * D_ + ld4];

    for (int tile = 0; tile < 9; tile++) {
        const int m0 = tile * 64;
        __syncthreads();                       // prev tile's MMAs done
        #pragma unroll
        for (int it = 0; it < 4; it++)
            *(uint4*)&sKV[lm[it] * SK_ST + ld4] = f2tf4(pre[it]);
        if (tile < 8) {
            const float* Kn = Kp + (m0 + 64) * D_;
            #pragma unroll
            for (int it = 0; it < 4; it++)
                pre[it] = *(const float4*)&Kn[lm[it] * D_ + ld4];
        }
        __syncthreads();

        float acc[2][4] = {};
        #pragma unroll
        for (int ks = 0; ks < 8; ks++) {
            int k0 = ks * 8;
            #pragma unroll
            for (int nt = 0; nt < 2; nt++) {
                int nb = cg + nt * 8;
                u32 bfr[2];
                bfr[0] = sKV[(nb + g) * SK_ST + k0 + tq    ];
                bfr[1] = sKV[(nb + g) * SK_ST + k0 + tq + 4];
                mma_tf32(acc[nt], qf[ks], bfr);
            }
        }
        #pragma unroll
        for (int nt = 0; nt < 2; nt++) {
            int c0 = m0 + cg + nt * 8 + 2 * tq;
            float2 v0; v0.x = acc[nt][0] * 0.125f; v0.y = acc[nt][1] * 0.125f;
            float2 v1; v1.x = acc[nt][2] * 0.125f; v1.y = acc[nt][3] * 0.125f;
            *(float2*)&sS[(roff + g    ) * SS_ST + c0] = v0;
            *(float2*)&sS[(roff + g + 8) * SS_ST + c0] = v1;
        }
    }

    // prefetch V tile 0 now — overlaps with softmax/blend below
    #pragma unroll
    for (int it = 0; it < 4; it++)
        pre[it] = *(const float4*)&Vp[lm[it] * D_ + ld4];

    __syncthreads();                           // all scores written

    // ---------------- Merged softmax + positional blend --------------------
    {
        const float gt = 1.f / (1.f + __expf(-gating[h]));
        const float c1 = 1.f - gt;
        const bool  tail = (lane < 16);

        for (int r = w; r < 32; r += 8) {      // warp-per-row, stats in regs
            float4* rowp4 = (float4*)(sS + r * SS_ST);
            float4 e4[5];
            float mx = -1e30f;
            #pragma unroll
            for (int i = 0; i < 4; i++) {
                e4[i] = rowp4[lane + 32 * i];
                mx = fmaxf(mx, fmaxf(fmaxf(e4[i].x, e4[i].y), fmaxf(e4[i].z, e4[i].w)));
            }
            if (tail) {
                e4[4] = rowp4[128 + lane];
                mx = fmaxf(mx, fmaxf(fmaxf(e4[4].x, e4[4].y), fmaxf(e4[4].z, e4[4].w)));
            } else {
                e4[4].x = e4[4].y = e4[4].z = e4[4].w = -1e30f;
            }
            #pragma unroll
            for (int o = 16; o; o >>= 1) mx = fmaxf(mx, __shfl_xor_sync(0xffffffffu, mx, o));

            float sum = 0.f;
            #pragma unroll
            for (int i = 0; i < 5; i++) {
                e4[i].x = __expf(e4[i].x - mx);
                e4[i].y = __expf(e4[i].y - mx);
                e4[i].z = __expf(e4[i].z - mx);
                e4[i].w = __expf(e4[i].w - mx);
                sum += (e4[i].x + e4[i].y) + (e4[i].z + e4[i].w);
            }
            #pragma unroll
            for (int o = 16; o; o >>= 1) sum += __shfl_xor_sync(0xffffffffu, sum, o);
            const float a = c1 / sum;

            const float4* sp4 = (const float4*)(g_SP + ((size_t)h * N_ + n0 + r) * N_);
            #pragma unroll
            for (int i = 0; i < 4; i++) {
                float4 s = sp4[lane + 32 * i];
                float4 o4;
                o4.x = a * e4[i].x + gt * s.x;
                o4.y = a * e4[i].y + gt * s.y;
                o4.z = a * e4[i].z + gt * s.z;
                o4.w = a * e4[i].w + gt * s.w;
                rowp4[lane + 32 * i] = o4;
            }
            if (tail) {
                float4 s = sp4[128 + lane];
                float4 o4;
                o4.x = a * e4[4].x + gt * s.x;
                o4.y = a * e4[4].y + gt * s.y;
                o4.z = a * e4[4].z + gt * s.z;
                o4.w = a * e4[4].w + gt * s.w;
                rowp4[128 + lane] = o4;
            }
        }
    }

    // ---------------- Phase D: out = W @ V via MMA --------------------------
    float accD[2][4] = {};
    for (int tile = 0; tile < 9; tile++) {
        const int m0 = tile * 64;
        __syncthreads();                       // blend done (tile 0) / prev MMAs done
        #pragma unroll
        for (int it = 0; it < 4; it++)
            *(uint4*)&sKV[lm[it] * SV_ST + ld4] = f2tf4(pre[it]);
        if (tile < 8) {
            const float* Vn = Vp + (m0 + 64) * D_;
            #pragma unroll
            for (int it = 0; it < 4; it++)
                pre[it] = *(const float4*)&Vn[lm[it] * D_ + ld4];
        }
        __syncthreads();

        #pragma unroll
        for (int ks = 0; ks < 8; ks++) {
            int k0 = m0 + ks * 8;
            u32 a[4];
            a[0] = f2tf(sS[(roff + g    ) * SS_ST + k0 + tq    ]);
            a[1] = f2tf(sS[(roff + g + 8) * SS_ST + k0 + tq    ]);
            a[2] = f2tf(sS[(roff + g    ) * SS_ST + k0 + tq + 4]);
            a[3] = f2tf(sS[(roff + g + 8) * SS_ST + k0 + tq + 4]);
            #pragma unroll
            for (int nt = 0; nt < 2; nt++) {
                int nb = cg + nt * 8;
                u32 bfr[2];
                bfr[0] = sKV[(ks * 8 + tq    ) * SV_ST + nb + g];
                bfr[1] = sKV[(ks * 8 + tq + 4) * SV_ST + nb + g];
                mma_tf32(accD[nt], a, bfr);
            }
        }
    }

    float* Op = g_AO + ((size_t)(b * N_ + n0)) * C_ + h * D_;
    #pragma unroll
    for (int nt = 0; nt < 2; nt++) {
        int c0 = cg + nt * 8 + 2 * tq;
        float2 v0; v0.x = accD[nt][0]; v0.y = accD[nt][1];
        float2 v1; v1.x = accD[nt][2]; v1.y = accD[nt][3];
        *(float2*)&Op[(roff + g    ) * C_ + c0] = v0;
        *(float2*)&Op[(roff + g + 8) * C_ + c0] = v1;
    }
}

// ===========================================================================
extern "C" void kernel_launch(void* const* d_in, const int* in_sizes, int n_in,
                              void* d_out, int out_size)
{
    const float* x      = (const float*)d_in[0];
    const float* Wq     = (const float*)d_in[1];
    const float* Wk     = (const float*)d_in[2];
    const float* Wv     = (const float*)d_in[3];
    const float* Wproj  = (const float*)d_in[4];
    const float* bproj  = (const float*)d_in[5];
    const float* pos_w  = (const float*)d_in[6];
    const float* pos_b  = (const float*)d_in[7];
    const float* gating = (const float*)d_in[8];
    float* out = (float*)d_out;

    const size_t attn_smem = ATTN_SMEM_WORDS * sizeof(u32);   // ~99 KB
    cudaFuncSetAttribute(attn_kernel, cudaFuncAttributeMaxDynamicSharedMemorySize,
                         (int)attn_smem);

    qkv_mma_kernel<<<dim3(B_ * N_ / 128, C_ / 128, 3), 256>>>(x, Wq, Wk, Wv);
    pos_kernel<<<(H_ * N_) / 8, 256>>>(pos_w, pos_b);
    attn_kernel<<<dim3(N_ / 32, H_, B_), 256, attn_smem>>>(gating);
    proj_mma_kernel<<<dim3(B_ * N_ / 128, C_ / 128), 256>>>(Wproj, bproj, out);
}

// round 11
// speedup vs baseline: 3.6345x; 1.0549x over previous
#include <cuda_runtime.h>

typedef unsigned int u32;

// Problem constants (fixed by the dataset)
#define B_  16
#define H_  12
#define N_  576
#define D_  64
#define C_  768
#define GW_ 24

// ---- scratch ----
__device__ float g_Q [B_*H_*N_*D_];
__device__ float g_K [B_*H_*N_*D_];
__device__ float g_V [B_*H_*N_*D_];
__device__ float g_AO[B_*N_*C_];
__device__ float g_SP[H_*N_*N_];      // positional softmax table (L2-resident, 15.9MB)

// ---------------------------------------------------------------------------
// TF32 helpers
// ---------------------------------------------------------------------------
__device__ __forceinline__ u32 f2tf(float f) {
    u32 u;
    asm("cvt.rna.tf32.f32 %0, %1;" : "=r"(u) : "f"(f));
    return u;
}
// Fragment mapping (m16n8k8, verified):
//   A: a0=(m=g,k=tq) a1=(m=g+8,k=tq) a2=(m=g,k=tq+4) a3=(m=g+8,k=tq+4)
//   B: b0=(k=tq,n=g) b1=(k=tq+4,n=g)
//   C: c0=(m=g,n=2tq) c1=(g,2tq+1) c2=(g+8,2tq) c3=(g+8,2tq+1)
__device__ __forceinline__ void mma_tf32(float* d, const u32* a, const u32* b) {
    asm volatile(
        "mma.sync.aligned.m16n8k8.row.col.f32.tf32.tf32.f32 "
        "{%0,%1,%2,%3}, {%4,%5,%6,%7}, {%8,%9}, {%0,%1,%2,%3};"
        : "+f"(d[0]), "+f"(d[1]), "+f"(d[2]), "+f"(d[3])
        : "r"(a[0]), "r"(a[1]), "r"(a[2]), "r"(a[3]), "r"(b[0]), "r"(b[1]));
}

__device__ __forceinline__ uint4 f2tf4(float4 v) {
    uint4 u; u.x = f2tf(v.x); u.y = f2tf(v.y); u.z = f2tf(v.z); u.w = f2tf(v.w);
    return u;
}

// ===========================================================================
// TF32 GEMM core: 128x128 tile, BK=16, 8 warps x (32x64) warp tiles.
// DOUBLE-BUFFERED smem mainloop: one __syncthreads per K-iter; STS of the
// next tile overlaps MMAs of the current tile.
// Conflict-free layouts:
//   sA [m=128][SA_ST=68]: frag banks = 4g+tq (+0/8) -> 32 distinct.
//   sB [k=16][SB_ST=136]: frag banks = 8tq+g       -> 32 distinct.
// ===========================================================================
#define SA_ST 68
#define SB_ST 136
#define A_WORDS (128 * SA_ST)         // 8704
#define BUF_WORDS (A_WORDS + 16 * SB_ST)   // 10880
#define GEMM_SMEM_BYTES (2 * BUF_WORDS * 4)  // 87040

#define EPI_QKV  0
#define EPI_PROJ 1

template<int EPI>
__device__ __forceinline__ void gemm_tf32_body(
    const float* __restrict__ A, const float* __restrict__ Wm,
    int row0, int col0,
    float* __restrict__ dst, const float* __restrict__ bias)
{
    extern __shared__ __align__(16) u32 dynsm[];

    const int t    = threadIdx.x;
    const int w    = t >> 5;
    const int lane = t & 31;
    const int g    = lane >> 2;
    const int tq   = lane & 3;
    const int m0w  = (w & 3) * 32;
    const int n0w  = (w >> 2) * 64;

    const int ar = t >> 2;            // 0..63 (rows ar, ar+64)
    const int ak = (t & 3) * 4;       // 0,4,8,12
    const int bk = t >> 5;            // 0..7  (k rows bk, bk+8)
    const int bn = (t & 31) * 4;

    float acc[2][8][4] = {};
    float4 ra0, ra1, rb0, rb1;

    // ---- prologue: tile 0 -> regs -> buf0; tile 1 -> regs ----
    ra0 = *(const float4*)&A [(row0 + ar     ) * C_ + ak];
    ra1 = *(const float4*)&A [(row0 + ar + 64) * C_ + ak];
    rb0 = *(const float4*)&Wm[(bk    ) * C_ + col0 + bn];
    rb1 = *(const float4*)&Wm[(bk + 8) * C_ + col0 + bn];
    {
        u32* sA = dynsm;
        u32* sB = dynsm + A_WORDS;
        *(uint4*)&sA[(ar     ) * SA_ST + ak] = f2tf4(ra0);
        *(uint4*)&sA[(ar + 64) * SA_ST + ak] = f2tf4(ra1);
        *(uint4*)&sB[(bk     ) * SB_ST + bn] = f2tf4(rb0);
        *(uint4*)&sB[(bk + 8 ) * SB_ST + bn] = f2tf4(rb1);
    }
    ra0 = *(const float4*)&A [(row0 + ar     ) * C_ + 16 + ak];
    ra1 = *(const float4*)&A [(row0 + ar + 64) * C_ + 16 + ak];
    rb0 = *(const float4*)&Wm[(16 + bk    ) * C_ + col0 + bn];
    rb1 = *(const float4*)&Wm[(16 + bk + 8) * C_ + col0 + bn];
    __syncthreads();

    const int NIT = C_ / 16;          // 48
    for (int it = 0; it < NIT; it++) {
        const u32* sA = dynsm + (it & 1) * BUF_WORDS;
        const u32* sB = sA + A_WORDS;

        // MMAs on current buffer
        #pragma unroll
        for (int ks = 0; ks < 16; ks += 8) {
            u32 af[2][4], bf[8][2];
            #pragma unroll
            for (int mb = 0; mb < 2; mb++) {
                int mrow = m0w + mb * 16 + g;
                af[mb][0] = sA[(mrow    ) * SA_ST + ks + tq    ];
                af[mb][1] = sA[(mrow + 8) * SA_ST + ks + tq    ];
                af[mb][2] = sA[(mrow    ) * SA_ST + ks + tq + 4];
                af[mb][3] = sA[(mrow + 8) * SA_ST + ks + tq + 4];
            }
            #pragma unroll
            for (int nb = 0; nb < 8; nb++) {
                int nc = n0w + nb * 8 + g;
                bf[nb][0] = sB[(ks + tq    ) * SB_ST + nc];
                bf[nb][1] = sB[(ks + tq + 4) * SB_ST + nc];
            }
            #pragma unroll
            for (int mb = 0; mb < 2; mb++)
                #pragma unroll
                for (int nb = 0; nb < 8; nb++)
                    mma_tf32(acc[mb][nb], af[mb], bf[nb]);
        }

        // store staged regs (tile it+1) into the other buffer, then
        // start loading tile it+2
        if (it + 1 < NIT) {
            u32* nA = dynsm + ((it + 1) & 1) * BUF_WORDS;
            u32* nB = nA + A_WORDS;
            *(uint4*)&nA[(ar     ) * SA_ST + ak] = f2tf4(ra0);
            *(uint4*)&nA[(ar + 64) * SA_ST + ak] = f2tf4(ra1);
            *(uint4*)&nB[(bk     ) * SB_ST + bn] = f2tf4(rb0);
            *(uint4*)&nB[(bk + 8 ) * SB_ST + bn] = f2tf4(rb1);
            if (it + 2 < NIT) {
                int k0 = (it + 2) * 16;
                ra0 = *(const float4*)&A [(row0 + ar     ) * C_ + k0 + ak];
                ra1 = *(const float4*)&A [(row0 + ar + 64) * C_ + k0 + ak];
                rb0 = *(const float4*)&Wm[(k0 + bk    ) * C_ + col0 + bn];
                rb1 = *(const float4*)&Wm[(k0 + bk + 8) * C_ + col0 + bn];
            }
        }
        __syncthreads();
    }

    // epilogue: float2 stores (cols 2tq, 2tq+1 are adjacent)
    #pragma unroll
    for (int mb = 0; mb < 2; mb++) {
        int r0 = row0 + m0w + mb * 16 + g;
        #pragma unroll
        for (int nb = 0; nb < 8; nb++) {
            int c0 = col0 + n0w + nb * 8 + 2 * tq;
            #pragma unroll
            for (int rr = 0; rr < 2; rr++) {
                int row = r0 + rr * 8;
                float2 v;
                v.x = acc[mb][nb][rr * 2 + 0];
                v.y = acc[mb][nb][rr * 2 + 1];
                if (EPI == EPI_QKV) {
                    int b  = row / N_;
                    int n  = row - b * N_;
                    int hh = c0 >> 6;
                    int dd = c0 & 63;       // even, dd+1 in same head
                    *(float2*)&dst[(((b * H_ + hh) * N_) + n) * D_ + dd] = v;
                } else {
                    v.x += bias[c0];
                    v.y += bias[c0 + 1];
                    *(float2*)&dst[(size_t)row * C_ + c0] = v;
                }
            }
        }
    }
}

__global__ __launch_bounds__(256, 2) void qkv_mma_kernel(
    const float* __restrict__ x,
    const float* __restrict__ Wq,
    const float* __restrict__ Wk,
    const float* __restrict__ Wv)
{
    const float* W   = (blockIdx.z == 0) ? Wq : (blockIdx.z == 1) ? Wk : Wv;
    float*       dst = (blockIdx.z == 0) ? g_Q : (blockIdx.z == 1) ? g_K : g_V;
    gemm_tf32_body<EPI_QKV>(x, W, blockIdx.x * 128, blockIdx.y * 128, dst, 0);
}

__global__ __launch_bounds__(256, 2) void proj_mma_kernel(
    const float* __restrict__ Wproj,
    const float* __restrict__ bproj,
    float* __restrict__ out)
{
    gemm_tf32_body<EPI_PROJ>(g_AO, Wproj, blockIdx.x * 128, blockIdx.y * 128,
                             out, bproj);
}

// ===========================================================================
// K2: positional softmax table S_pos[h][n][m]. One warp per (h,n) row.
// ===========================================================================
__global__ __launch_bounds__(256) void pos_kernel(
    const float* __restrict__ pos_w,
    const float* __restrict__ pos_b)
{
    const int warp = threadIdx.x >> 5;
    const int lane = threadIdx.x & 31;
    const int row  = blockIdx.x * 8 + warp;
    const int h    = row / N_;
    const int n    = row - h * N_;

    const float wx = pos_w[0 * H_ + h];
    const float wy = pos_w[1 * H_ + h];
    const float wz = pos_w[2 * H_ + h];
    const float pb = pos_b[h];
    const int nx = n % GW_, ny = n / GW_;

    float buf[18];
    float mx = -1e30f;
    #pragma unroll
    for (int i = 0; i < 18; i++) {
        int m  = lane + 32 * i;
        float fdx = (float)((m % GW_) - nx);
        float fdy = (float)((m / GW_) - ny);
        float s = wx * fdx + wy * fdy + wz * (fdx * fdx + fdy * fdy) + pb;
        buf[i] = s;
        mx = fmaxf(mx, s);
    }
    #pragma unroll
    for (int o = 16; o; o >>= 1) mx = fmaxf(mx, __shfl_xor_sync(0xffffffffu, mx, o));

    float sum = 0.f;
    #pragma unroll
    for (int i = 0; i < 18; i++) { buf[i] = __expf(buf[i] - mx); sum += buf[i]; }
    #pragma unroll
    for (int o = 16; o; o >>= 1) sum += __shfl_xor_sync(0xffffffffu, sum, o);

    const float inv = 1.f / sum;
    float* dstp = g_SP + (size_t)row * N_;
    #pragma unroll
    for (int i = 0; i < 18; i++) dstp[lane + 32 * i] = buf[i] * inv;
}

// ===========================================================================
// K3: fused attention, TF32 MMA.
//  - Q fragments hoisted to registers (loop-invariant over the 9 K tiles).
//  - Register-prefetch of next K/V tile (LDG overlaps MMA).
//  - Merged softmax+blend writes weights ALREADY converted to tf32 bit
//    patterns, so phase D loads fragments with plain LDS (no CVT).
// Bank-verified strides: sQ/sK 68, sV 72, sS 580 (all conflict-free).
// ===========================================================================
#define SQ_ST 68
#define SK_ST 68
#define SV_ST 72
#define SS_ST 580
#define ATTN_SMEM_WORDS (32*SQ_ST + 64*SV_ST + 32*SS_ST)

__global__ __launch_bounds__(256, 2) void attn_kernel(const float* __restrict__ gating)
{
    extern __shared__ __align__(16) u32 smw[];
    u32*   sQ   = smw;                        // tf32 [32][SQ_ST]
    u32*   sKV  = sQ + 32 * SQ_ST;            // tf32 K [64][SK_ST] / V [64][SV_ST]
    float* sS   = (float*)(sKV + 64 * SV_ST); // fp32 scores -> tf32 weights [32][SS_ST]
    u32*   sSw  = (u32*)sS;

    const int b  = blockIdx.z;
    const int h  = blockIdx.y;
    const int n0 = blockIdx.x * 32;
    const int t  = threadIdx.x;
    const int w    = t >> 5;
    const int lane = t & 31;
    const int g    = lane >> 2;
    const int tq   = lane & 3;
    const int roff = (w & 1) * 16;     // row half
    const int cg   = (w >> 1) * 16;    // col group within 64

    const float* Qp = g_Q + (((size_t)(b * H_ + h)) * N_ + n0) * D_;
    const float* Kp = g_K + ((size_t)(b * H_ + h)) * N_ * D_;
    const float* Vp = g_V + ((size_t)(b * H_ + h)) * N_ * D_;

    // tile-loader index map (64x64 tile, 4 float4 per thread)
    const int lm[4] = { (t + 0) >> 4, (t + 256) >> 4, (t + 512) >> 4, (t + 768) >> 4 };
    const int ld4   = (t & 15) << 2;

    // load Q tile (tf32) into sQ[m][d]
    for (int i = t; i < 32 * 16; i += 256) {
        int n  = i >> 4;
        int d4 = (i & 15) << 2;
        *(uint4*)&sQ[n * SQ_ST + d4] = f2tf4(*(const float4*)&Qp[n * D_ + d4]);
    }
    __syncthreads();

    // hoist Q fragments (invariant across K tiles)
    u32 qf[8][4];
    #pragma unroll
    for (int ks = 0; ks < 8; ks++) {
        int k0 = ks * 8;
        qf[ks][0] = sQ[(roff + g    ) * SQ_ST + k0 + tq    ];
        qf[ks][1] = sQ[(roff + g + 8) * SQ_ST + k0 + tq    ];
        qf[ks][2] = sQ[(roff + g    ) * SQ_ST + k0 + tq + 4];
        qf[ks][3] = sQ[(roff + g + 8) * SQ_ST + k0 + tq + 4];
    }

    // ---------------- Phase A: scores via MMA (prefetched tiles) -----------
    float4 pre[4];
    #pragma unroll
    for (int it = 0; it < 4; it++)
        pre[it] = *(const float4*)&Kp[lm[it] * D_ + ld4];

    for (int tile = 0; tile < 9; tile++) {
        const int m0 = tile * 64;
        __syncthreads();                       // prev tile's MMAs done
        #pragma unroll
        for (int it = 0; it < 4; it++)
            *(uint4*)&sKV[lm[it] * SK_ST + ld4] = f2tf4(pre[it]);
        if (tile < 8) {
            const float* Kn = Kp + (m0 + 64) * D_;
            #pragma unroll
            for (int it = 0; it < 4; it++)
                pre[it] = *(const float4*)&Kn[lm[it] * D_ + ld4];
        }
        __syncthreads();

        float acc[2][4] = {};
        #pragma unroll
        for (int ks = 0; ks < 8; ks++) {
            int k0 = ks * 8;
            #pragma unroll
            for (int nt = 0; nt < 2; nt++) {
                int nb = cg + nt * 8;
                u32 bfr[2];
                bfr[0] = sKV[(nb + g) * SK_ST + k0 + tq    ];
                bfr[1] = sKV[(nb + g) * SK_ST + k0 + tq + 4];
                mma_tf32(acc[nt], qf[ks], bfr);
            }
        }
        #pragma unroll
        for (int nt = 0; nt < 2; nt++) {
            int c0 = m0 + cg + nt * 8 + 2 * tq;
            float2 v0; v0.x = acc[nt][0] * 0.125f; v0.y = acc[nt][1] * 0.125f;
            float2 v1; v1.x = acc[nt][2] * 0.125f; v1.y = acc[nt][3] * 0.125f;
            *(float2*)&sS[(roff + g    ) * SS_ST + c0] = v0;
            *(float2*)&sS[(roff + g + 8) * SS_ST + c0] = v1;
        }
    }

    // prefetch V tile 0 now — overlaps with softmax/blend below
    #pragma unroll
    for (int it = 0; it < 4; it++)
        pre[it] = *(const float4*)&Vp[lm[it] * D_ + ld4];

    __syncthreads();                           // all scores written

    // ---------------- Merged softmax + positional blend (tf32 out) ---------
    {
        const float gt = 1.f / (1.f + __expf(-gating[h]));
        const float c1 = 1.f - gt;
        const bool  tail = (lane < 16);

        for (int r = w; r < 32; r += 8) {      // warp-per-row, stats in regs
            float4* rowp4 = (float4*)(sS + r * SS_ST);
            uint4*  rowp4u = (uint4*)rowp4;
            float4 e4[5];
            float mx = -1e30f;
            #pragma unroll
            for (int i = 0; i < 4; i++) {
                e4[i] = rowp4[lane + 32 * i];
                mx = fmaxf(mx, fmaxf(fmaxf(e4[i].x, e4[i].y), fmaxf(e4[i].z, e4[i].w)));
            }
            if (tail) {
                e4[4] = rowp4[128 + lane];
                mx = fmaxf(mx, fmaxf(fmaxf(e4[4].x, e4[4].y), fmaxf(e4[4].z, e4[4].w)));
            } else {
                e4[4].x = e4[4].y = e4[4].z = e4[4].w = -1e30f;
            }
            #pragma unroll
            for (int o = 16; o; o >>= 1) mx = fmaxf(mx, __shfl_xor_sync(0xffffffffu, mx, o));

            float sum = 0.f;
            #pragma unroll
            for (int i = 0; i < 5; i++) {
                e4[i].x = __expf(e4[i].x - mx);
                e4[i].y = __expf(e4[i].y - mx);
                e4[i].z = __expf(e4[i].z - mx);
                e4[i].w = __expf(e4[i].w - mx);
                sum += (e4[i].x + e4[i].y) + (e4[i].z + e4[i].w);
            }
            #pragma unroll
            for (int o = 16; o; o >>= 1) sum += __shfl_xor_sync(0xffffffffu, sum, o);
            const float a = c1 / sum;

            const float4* sp4 = (const float4*)(g_SP + ((size_t)h * N_ + n0 + r) * N_);
            #pragma unroll
            for (int i = 0; i < 4; i++) {
                float4 s = sp4[lane + 32 * i];
                uint4 o4;
                o4.x = f2tf(a * e4[i].x + gt * s.x);
                o4.y = f2tf(a * e4[i].y + gt * s.y);
                o4.z = f2tf(a * e4[i].z + gt * s.z);
                o4.w = f2tf(a * e4[i].w + gt * s.w);
                rowp4u[lane + 32 * i] = o4;
            }
            if (tail) {
                float4 s = sp4[128 + lane];
                uint4 o4;
                o4.x = f2tf(a * e4[4].x + gt * s.x);
                o4.y = f2tf(a * e4[4].y + gt * s.y);
                o4.z = f2tf(a * e4[4].z + gt * s.z);
                o4.w = f2tf(a * e4[4].w + gt * s.w);
                rowp4u[128 + lane] = o4;
            }
        }
    }

    // ---------------- Phase D: out = W @ V via MMA --------------------------
    float accD[2][4] = {};
    for (int tile = 0; tile < 9; tile++) {
        const int m0 = tile * 64;
        __syncthreads();                       // blend done (tile 0) / prev MMAs done
        #pragma unroll
        for (int it = 0; it < 4; it++)
            *(uint4*)&sKV[lm[it] * SV_ST + ld4] = f2tf4(pre[it]);
        if (tile < 8) {
            const float* Vn = Vp + (m0 + 64) * D_;
            #pragma unroll
            for (int it = 0; it < 4; it++)
                pre[it] = *(const float4*)&Vn[lm[it] * D_ + ld4];
        }
        __syncthreads();

        #pragma unroll
        for (int ks = 0; ks < 8; ks++) {
            int k0 = m0 + ks * 8;
            u32 a[4];
            a[0] = sSw[(roff + g    ) * SS_ST + k0 + tq    ];
            a[1] = sSw[(roff + g + 8) * SS_ST + k0 + tq    ];
            a[2] = sSw[(roff + g    ) * SS_ST + k0 + tq + 4];
            a[3] = sSw[(roff + g + 8) * SS_ST + k0 + tq + 4];
            #pragma unroll
            for (int nt = 0; nt < 2; nt++) {
                int nb = cg + nt * 8;
                u32 bfr[2];
                bfr[0] = sKV[(ks * 8 + tq    ) * SV_ST + nb + g];
                bfr[1] = sKV[(ks * 8 + tq + 4) * SV_ST + nb + g];
                mma_tf32(accD[nt], a, bfr);
            }
        }
    }

    float* Op = g_AO + ((size_t)(b * N_ + n0)) * C_ + h * D_;
    #pragma unroll
    for (int nt = 0; nt < 2; nt++) {
        int c0 = cg + nt * 8 + 2 * tq;
        float2 v0; v0.x = accD[nt][0]; v0.y = accD[nt][1];
        float2 v1; v1.x = accD[nt][2]; v1.y = accD[nt][3];
        *(float2*)&Op[(roff + g    ) * C_ + c0] = v0;
        *(float2*)&Op[(roff + g + 8) * C_ + c0] = v1;
    }
}

// ===========================================================================
extern "C" void kernel_launch(void* const* d_in, const int* in_sizes, int n_in,
                              void* d_out, int out_size)
{
    const float* x      = (const float*)d_in[0];
    const float* Wq     = (const float*)d_in[1];
    const float* Wk     = (const float*)d_in[2];
    const float* Wv     = (const float*)d_in[3];
    const float* Wproj  = (const float*)d_in[4];
    const float* bproj  = (const float*)d_in[5];
    const float* pos_w  = (const float*)d_in[6];
    const float* pos_b  = (const float*)d_in[7];
    const float* gating = (const float*)d_in[8];
    float* out = (float*)d_out;

    const size_t attn_smem = ATTN_SMEM_WORDS * sizeof(u32);   // ~99 KB
    cudaFuncSetAttribute(attn_kernel, cudaFuncAttributeMaxDynamicSharedMemorySize,
                         (int)attn_smem);
    cudaFuncSetAttribute(qkv_mma_kernel, cudaFuncAttributeMaxDynamicSharedMemorySize,
                         GEMM_SMEM_BYTES);
    cudaFuncSetAttribute(proj_mma_kernel, cudaFuncAttributeMaxDynamicSharedMemorySize,
                         GEMM_SMEM_BYTES);

    qkv_mma_kernel<<<dim3(B_ * N_ / 128, C_ / 128, 3), 256, GEMM_SMEM_BYTES>>>(x, Wq, Wk, Wv);
    pos_kernel<<<(H_ * N_) / 8, 256>>>(pos_w, pos_b);
    attn_kernel<<<dim3(N_ / 32, H_, B_), 256, attn_smem>>>(gating);
    proj_mma_kernel<<<dim3(B_ * N_ / 128, C_ / 128), 256, GEMM_SMEM_BYTES>>>(Wproj, bproj, out);
}

// round 12
// speedup vs baseline: 3.8030x; 1.0464x over previous
#include <cuda_runtime.h>

typedef unsigned int u32;

// Problem constants (fixed by the dataset)
#define B_  16
#define H_  12
#define N_  576
#define D_  64
#define C_  768
#define GW_ 24

// ---- scratch ----
__device__ float g_Q [B_*H_*N_*D_];
__device__ float g_K [B_*H_*N_*D_];
__device__ float g_V [B_*H_*N_*D_];
__device__ float g_AO[B_*N_*C_];
__device__ float g_SP[H_*N_*N_];      // positional softmax table (L2-resident, 15.9MB)

// ---------------------------------------------------------------------------
// TF32 helpers
// ---------------------------------------------------------------------------
__device__ __forceinline__ u32 f2tf(float f) {
    u32 u;
    asm("cvt.rna.tf32.f32 %0, %1;" : "=r"(u) : "f"(f));
    return u;
}
// Fragment mapping (m16n8k8, verified):
//   A: a0=(m=g,k=tq) a1=(m=g+8,k=tq) a2=(m=g,k=tq+4) a3=(m=g+8,k=tq+4)
//   B: b0=(k=tq,n=g) b1=(k=tq+4,n=g)
//   C: c0=(m=g,n=2tq) c1=(g,2tq+1) c2=(g+8,2tq) c3=(g+8,2tq+1)
__device__ __forceinline__ void mma_tf32(float* d, const u32* a, const u32* b) {
    asm volatile(
        "mma.sync.aligned.m16n8k8.row.col.f32.tf32.tf32.f32 "
        "{%0,%1,%2,%3}, {%4,%5,%6,%7}, {%8,%9}, {%0,%1,%2,%3};"
        : "+f"(d[0]), "+f"(d[1]), "+f"(d[2]), "+f"(d[3])
        : "r"(a[0]), "r"(a[1]), "r"(a[2]), "r"(a[3]), "r"(b[0]), "r"(b[1]));
}

__device__ __forceinline__ uint4 f2tf4(float4 v) {
    uint4 u; u.x = f2tf(v.x); u.y = f2tf(v.y); u.z = f2tf(v.z); u.w = f2tf(v.w);
    return u;
}

// ===========================================================================
// TF32 GEMM core: 128x128 tile, BK=16, 8 warps x (32x64) warp tiles.
// Double-buffered smem mainloop (one barrier per K-iter).
// Conflict-free layouts: sA [m][68], sB [k][136].
// ===========================================================================
#define SA_ST 68
#define SB_ST 136
#define A_WORDS (128 * SA_ST)
#define BUF_WORDS (A_WORDS + 16 * SB_ST)
#define GEMM_SMEM_BYTES (2 * BUF_WORDS * 4)

#define EPI_QKV  0
#define EPI_PROJ 1

template<int EPI>
__device__ __forceinline__ void gemm_tf32_body(
    const float* __restrict__ A, const float* __restrict__ Wm,
    int row0, int col0,
    float* __restrict__ dst, const float* __restrict__ bias)
{
    extern __shared__ __align__(16) u32 dynsm[];

    const int t    = threadIdx.x;
    const int w    = t >> 5;
    const int lane = t & 31;
    const int g    = lane >> 2;
    const int tq   = lane & 3;
    const int m0w  = (w & 3) * 32;
    const int n0w  = (w >> 2) * 64;

    const int ar = t >> 2;
    const int ak = (t & 3) * 4;
    const int bk = t >> 5;
    const int bn = (t & 31) * 4;

    float acc[2][8][4] = {};
    float4 ra0, ra1, rb0, rb1;

    ra0 = *(const float4*)&A [(row0 + ar     ) * C_ + ak];
    ra1 = *(const float4*)&A [(row0 + ar + 64) * C_ + ak];
    rb0 = *(const float4*)&Wm[(bk    ) * C_ + col0 + bn];
    rb1 = *(const float4*)&Wm[(bk + 8) * C_ + col0 + bn];
    {
        u32* sA = dynsm;
        u32* sB = dynsm + A_WORDS;
        *(uint4*)&sA[(ar     ) * SA_ST + ak] = f2tf4(ra0);
        *(uint4*)&sA[(ar + 64) * SA_ST + ak] = f2tf4(ra1);
        *(uint4*)&sB[(bk     ) * SB_ST + bn] = f2tf4(rb0);
        *(uint4*)&sB[(bk + 8 ) * SB_ST + bn] = f2tf4(rb1);
    }
    ra0 = *(const float4*)&A [(row0 + ar     ) * C_ + 16 + ak];
    ra1 = *(const float4*)&A [(row0 + ar + 64) * C_ + 16 + ak];
    rb0 = *(const float4*)&Wm[(16 + bk    ) * C_ + col0 + bn];
    rb1 = *(const float4*)&Wm[(16 + bk + 8) * C_ + col0 + bn];
    __syncthreads();

    const int NIT = C_ / 16;
    for (int it = 0; it < NIT; it++) {
        const u32* sA = dynsm + (it & 1) * BUF_WORDS;
        const u32* sB = sA + A_WORDS;

        #pragma unroll
        for (int ks = 0; ks < 16; ks += 8) {
            u32 af[2][4], bf[8][2];
            #pragma unroll
            for (int mb = 0; mb < 2; mb++) {
                int mrow = m0w + mb * 16 + g;
                af[mb][0] = sA[(mrow    ) * SA_ST + ks + tq    ];
                af[mb][1] = sA[(mrow + 8) * SA_ST + ks + tq    ];
                af[mb][2] = sA[(mrow    ) * SA_ST + ks + tq + 4];
                af[mb][3] = sA[(mrow + 8) * SA_ST + ks + tq + 4];
            }
            #pragma unroll
            for (int nb = 0; nb < 8; nb++) {
                int nc = n0w + nb * 8 + g;
                bf[nb][0] = sB[(ks + tq    ) * SB_ST + nc];
                bf[nb][1] = sB[(ks + tq + 4) * SB_ST + nc];
            }
            #pragma unroll
            for (int mb = 0; mb < 2; mb++)
                #pragma unroll
                for (int nb = 0; nb < 8; nb++)
                    mma_tf32(acc[mb][nb], af[mb], bf[nb]);
        }

        if (it + 1 < NIT) {
            u32* nA = dynsm + ((it + 1) & 1) * BUF_WORDS;
            u32* nB = nA + A_WORDS;
            *(uint4*)&nA[(ar     ) * SA_ST + ak] = f2tf4(ra0);
            *(uint4*)&nA[(ar + 64) * SA_ST + ak] = f2tf4(ra1);
            *(uint4*)&nB[(bk     ) * SB_ST + bn] = f2tf4(rb0);
            *(uint4*)&nB[(bk + 8 ) * SB_ST + bn] = f2tf4(rb1);
            if (it + 2 < NIT) {
                int k0 = (it + 2) * 16;
                ra0 = *(const float4*)&A [(row0 + ar     ) * C_ + k0 + ak];
                ra1 = *(const float4*)&A [(row0 + ar + 64) * C_ + k0 + ak];
                rb0 = *(const float4*)&Wm[(k0 + bk    ) * C_ + col0 + bn];
                rb1 = *(const float4*)&Wm[(k0 + bk + 8) * C_ + col0 + bn];
            }
        }
        __syncthreads();
    }

    #pragma unroll
    for (int mb = 0; mb < 2; mb++) {
        int r0 = row0 + m0w + mb * 16 + g;
        #pragma unroll
        for (int nb = 0; nb < 8; nb++) {
            int c0 = col0 + n0w + nb * 8 + 2 * tq;
            #pragma unroll
            for (int rr = 0; rr < 2; rr++) {
                int row = r0 + rr * 8;
                float2 v;
                v.x = acc[mb][nb][rr * 2 + 0];
                v.y = acc[mb][nb][rr * 2 + 1];
                if (EPI == EPI_QKV) {
                    int b  = row / N_;
                    int n  = row - b * N_;
                    int hh = c0 >> 6;
                    int dd = c0 & 63;
                    *(float2*)&dst[(((b * H_ + hh) * N_) + n) * D_ + dd] = v;
                } else {
                    v.x += bias[c0];
                    v.y += bias[c0 + 1];
                    *(float2*)&dst[(size_t)row * C_ + c0] = v;
                }
            }
        }
    }
}

__global__ __launch_bounds__(256, 2) void qkv_mma_kernel(
    const float* __restrict__ x,
    const float* __restrict__ Wq,
    const float* __restrict__ Wk,
    const float* __restrict__ Wv)
{
    const float* W   = (blockIdx.z == 0) ? Wq : (blockIdx.z == 1) ? Wk : Wv;
    float*       dst = (blockIdx.z == 0) ? g_Q : (blockIdx.z == 1) ? g_K : g_V;
    gemm_tf32_body<EPI_QKV>(x, W, blockIdx.x * 128, blockIdx.y * 128, dst, 0);
}

__global__ __launch_bounds__(256, 2) void proj_mma_kernel(
    const float* __restrict__ Wproj,
    const float* __restrict__ bproj,
    float* __restrict__ out)
{
    gemm_tf32_body<EPI_PROJ>(g_AO, Wproj, blockIdx.x * 128, blockIdx.y * 128,
                             out, bproj);
}

// ===========================================================================
// K2: positional softmax table S_pos[h][n][m]. One warp per (h,n) row.
// ===========================================================================
__global__ __launch_bounds__(256) void pos_kernel(
    const float* __restrict__ pos_w,
    const float* __restrict__ pos_b)
{
    const int warp = threadIdx.x >> 5;
    const int lane = threadIdx.x & 31;
    const int row  = blockIdx.x * 8 + warp;
    const int h    = row / N_;
    const int n    = row - h * N_;

    const float wx = pos_w[0 * H_ + h];
    const float wy = pos_w[1 * H_ + h];
    const float wz = pos_w[2 * H_ + h];
    const float pb = pos_b[h];
    const int nx = n % GW_, ny = n / GW_;

    float buf[18];
    float mx = -1e30f;
    #pragma unroll
    for (int i = 0; i < 18; i++) {
        int m  = lane + 32 * i;
        float fdx = (float)((m % GW_) - nx);
        float fdy = (float)((m / GW_) - ny);
        float s = wx * fdx + wy * fdy + wz * (fdx * fdx + fdy * fdy) + pb;
        buf[i] = s;
        mx = fmaxf(mx, s);
    }
    #pragma unroll
    for (int o = 16; o; o >>= 1) mx = fmaxf(mx, __shfl_xor_sync(0xffffffffu, mx, o));

    float sum = 0.f;
    #pragma unroll
    for (int i = 0; i < 18; i++) { buf[i] = __expf(buf[i] - mx); sum += buf[i]; }
    #pragma unroll
    for (int o = 16; o; o >>= 1) sum += __shfl_xor_sync(0xffffffffu, sum, o);

    const float inv = 1.f / sum;
    float* dstp = g_SP + (size_t)row * N_;
    #pragma unroll
    for (int i = 0; i < 18; i++) dstp[lane + 32 * i] = buf[i] * inv;
}

// ===========================================================================
// K3: fused attention, TF32 MMA, 64 QUERY ROWS PER BLOCK (512 threads).
// Halves K/V L2 traffic vs 32-row blocks. 16 warps: 4 row-halves x 4
// col-groups. Same per-warp MMA micro-structure as before.
// smem: sQ [64][68] + sKV [64][72] + sS [64][580] = 184 KB, 1 block/SM
// (same 16 warps/SM as the previous 2x256 configuration).
// ===========================================================================
#define SQ_ST 68
#define SK_ST 68
#define SV_ST 72
#define SS_ST 580
#define AROWS 64
#define ATHREADS 512
#define ATTN_SMEM_WORDS (AROWS*SQ_ST + AROWS*SV_ST + AROWS*SS_ST)

__global__ __launch_bounds__(ATHREADS, 1) void attn_kernel(const float* __restrict__ gating)
{
    extern __shared__ __align__(16) u32 smw[];
    u32*   sQ   = smw;                           // tf32 [64][SQ_ST]
    u32*   sKV  = sQ + AROWS * SQ_ST;            // tf32 K [64][SK_ST] / V [64][SV_ST]
    float* sS   = (float*)(sKV + AROWS * SV_ST); // fp32 scores -> tf32 weights [64][SS_ST]
    u32*   sSw  = (u32*)sS;

    const int b  = blockIdx.z;
    const int h  = blockIdx.y;
    const int n0 = blockIdx.x * AROWS;
    const int t  = threadIdx.x;
    const int w    = t >> 5;
    const int lane = t & 31;
    const int g    = lane >> 2;
    const int tq   = lane & 3;
    const int roff = (w & 3) * 16;     // row half: 0,16,32,48
    const int cg   = (w >> 2) * 16;    // col group within 64

    const float* Qp = g_Q + (((size_t)(b * H_ + h)) * N_ + n0) * D_;
    const float* Kp = g_K + ((size_t)(b * H_ + h)) * N_ * D_;
    const float* Vp = g_V + ((size_t)(b * H_ + h)) * N_ * D_;

    // tile-loader index map (64x64 tile, 2 float4 per thread @ 512 threads)
    const int lr0 = t >> 4;            // rows lr0, lr0+32
    const int ld4 = (t & 15) << 2;

    // load Q tile (tf32) into sQ[m][d] (64x64)
    *(uint4*)&sQ[(lr0     ) * SQ_ST + ld4] = f2tf4(*(const float4*)&Qp[(lr0     ) * D_ + ld4]);
    *(uint4*)&sQ[(lr0 + 32) * SQ_ST + ld4] = f2tf4(*(const float4*)&Qp[(lr0 + 32) * D_ + ld4]);
    __syncthreads();

    // hoist Q fragments (invariant across K tiles)
    u32 qf[8][4];
    #pragma unroll
    for (int ks = 0; ks < 8; ks++) {
        int k0 = ks * 8;
        qf[ks][0] = sQ[(roff + g    ) * SQ_ST + k0 + tq    ];
        qf[ks][1] = sQ[(roff + g + 8) * SQ_ST + k0 + tq    ];
        qf[ks][2] = sQ[(roff + g    ) * SQ_ST + k0 + tq + 4];
        qf[ks][3] = sQ[(roff + g + 8) * SQ_ST + k0 + tq + 4];
    }

    // ---------------- Phase A: scores via MMA (prefetched K tiles) ---------
    float4 pre0 = *(const float4*)&Kp[(lr0     ) * D_ + ld4];
    float4 pre1 = *(const float4*)&Kp[(lr0 + 32) * D_ + ld4];

    for (int tile = 0; tile < 9; tile++) {
        const int m0 = tile * 64;
        __syncthreads();                       // prev tile's MMAs done
        *(uint4*)&sKV[(lr0     ) * SK_ST + ld4] = f2tf4(pre0);
        *(uint4*)&sKV[(lr0 + 32) * SK_ST + ld4] = f2tf4(pre1);
        if (tile < 8) {
            const float* Kn = Kp + (m0 + 64) * D_;
            pre0 = *(const float4*)&Kn[(lr0     ) * D_ + ld4];
            pre1 = *(const float4*)&Kn[(lr0 + 32) * D_ + ld4];
        }
        __syncthreads();

        float acc[2][4] = {};
        #pragma unroll
        for (int ks = 0; ks < 8; ks++) {
            int k0 = ks * 8;
            #pragma unroll
            for (int nt = 0; nt < 2; nt++) {
                int nb = cg + nt * 8;
                u32 bfr[2];
                bfr[0] = sKV[(nb + g) * SK_ST + k0 + tq    ];
                bfr[1] = sKV[(nb + g) * SK_ST + k0 + tq + 4];
                mma_tf32(acc[nt], qf[ks], bfr);
            }
        }
        #pragma unroll
        for (int nt = 0; nt < 2; nt++) {
            int c0 = m0 + cg + nt * 8 + 2 * tq;
            float2 v0; v0.x = acc[nt][0] * 0.125f; v0.y = acc[nt][1] * 0.125f;
            float2 v1; v1.x = acc[nt][2] * 0.125f; v1.y = acc[nt][3] * 0.125f;
            *(float2*)&sS[(roff + g    ) * SS_ST + c0] = v0;
            *(float2*)&sS[(roff + g + 8) * SS_ST + c0] = v1;
        }
    }

    // prefetch V tile 0 — overlaps with softmax/blend below
    pre0 = *(const float4*)&Vp[(lr0     ) * D_ + ld4];
    pre1 = *(const float4*)&Vp[(lr0 + 32) * D_ + ld4];

    __syncthreads();                           // all scores written

    // ---------------- Merged softmax + positional blend (tf32 out) ---------
    {
        const float gt = 1.f / (1.f + __expf(-gating[h]));
        const float c1 = 1.f - gt;
        const bool  tail = (lane < 16);

        for (int r = w; r < AROWS; r += 16) {  // warp-per-row, stats in regs
            float4* rowp4 = (float4*)(sS + r * SS_ST);
            uint4*  rowp4u = (uint4*)rowp4;
            float4 e4[5];
            float mx = -1e30f;
            #pragma unroll
            for (int i = 0; i < 4; i++) {
                e4[i] = rowp4[lane + 32 * i];
                mx = fmaxf(mx, fmaxf(fmaxf(e4[i].x, e4[i].y), fmaxf(e4[i].z, e4[i].w)));
            }
            if (tail) {
                e4[4] = rowp4[128 + lane];
                mx = fmaxf(mx, fmaxf(fmaxf(e4[4].x, e4[4].y), fmaxf(e4[4].z, e4[4].w)));
            } else {
                e4[4].x = e4[4].y = e4[4].z = e4[4].w = -1e30f;
            }
            #pragma unroll
            for (int o = 16; o; o >>= 1) mx = fmaxf(mx, __shfl_xor_sync(0xffffffffu, mx, o));

            float sum = 0.f;
            #pragma unroll
            for (int i = 0; i < 5; i++) {
                e4[i].x = __expf(e4[i].x - mx);
                e4[i].y = __expf(e4[i].y - mx);
                e4[i].z = __expf(e4[i].z - mx);
                e4[i].w = __expf(e4[i].w - mx);
                sum += (e4[i].x + e4[i].y) + (e4[i].z + e4[i].w);
            }
            #pragma unroll
            for (int o = 16; o; o >>= 1) sum += __shfl_xor_sync(0xffffffffu, sum, o);
            const float a = c1 / sum;

            const float4* sp4 = (const float4*)(g_SP + ((size_t)h * N_ + n0 + r) * N_);
            #pragma unroll
            for (int i = 0; i < 4; i++) {
                float4 s = sp4[lane + 32 * i];
                uint4 o4;
                o4.x = f2tf(a * e4[i].x + gt * s.x);
                o4.y = f2tf(a * e4[i].y + gt * s.y);
                o4.z = f2tf(a * e4[i].z + gt * s.z);
                o4.w = f2tf(a * e4[i].w + gt * s.w);
                rowp4u[lane + 32 * i] = o4;
            }
            if (tail) {
                float4 s = sp4[128 + lane];
                uint4 o4;
                o4.x = f2tf(a * e4[4].x + gt * s.x);
                o4.y = f2tf(a * e4[4].y + gt * s.y);
                o4.z = f2tf(a * e4[4].z + gt * s.z);
                o4.w = f2tf(a * e4[4].w + gt * s.w);
                rowp4u[128 + lane] = o4;
            }
        }
    }

    // ---------------- Phase D: out = W @ V via MMA --------------------------
    float accD[2][4] = {};
    for (int tile = 0; tile < 9; tile++) {
        const int m0 = tile * 64;
        __syncthreads();                       // blend done / prev MMAs done
        *(uint4*)&sKV[(lr0     ) * SV_ST + ld4] = f2tf4(pre0);
        *(uint4*)&sKV[(lr0 + 32) * SV_ST + ld4] = f2tf4(pre1);
        if (tile < 8) {
            const float* Vn = Vp + (m0 + 64) * D_;
            pre0 = *(const float4*)&Vn[(lr0     ) * D_ + ld4];
            pre1 = *(const float4*)&Vn[(lr0 + 32) * D_ + ld4];
        }
        __syncthreads();

        #pragma unroll
        for (int ks = 0; ks < 8; ks++) {
            int k0 = m0 + ks * 8;
            u32 a[4];
            a[0] = sSw[(roff + g    ) * SS_ST + k0 + tq    ];
            a[1] = sSw[(roff + g + 8) * SS_ST + k0 + tq    ];
            a[2] = sSw[(roff + g    ) * SS_ST + k0 + tq + 4];
            a[3] = sSw[(roff + g + 8) * SS_ST + k0 + tq + 4];
            #pragma unroll
            for (int nt = 0; nt < 2; nt++) {
                int nb = cg + nt * 8;
                u32 bfr[2];
                bfr[0] = sKV[(ks * 8 + tq    ) * SV_ST + nb + g];
                bfr[1] = sKV[(ks * 8 + tq + 4) * SV_ST + nb + g];
                mma_tf32(accD[nt], a, bfr);
            }
        }
    }

    float* Op = g_AO + ((size_t)(b * N_ + n0)) * C_ + h * D_;
    #pragma unroll
    for (int nt = 0; nt < 2; nt++) {
        int c0 = cg + nt * 8 + 2 * tq;
        float2 v0; v0.x = accD[nt][0]; v0.y = accD[nt][1];
        float2 v1; v1.x = accD[nt][2]; v1.y = accD[nt][3];
        *(float2*)&Op[(roff + g    ) * C_ + c0] = v0;
        *(float2*)&Op[(roff + g + 8) * C_ + c0] = v1;
    }
}

// ===========================================================================
extern "C" void kernel_launch(void* const* d_in, const int* in_sizes, int n_in,
                              void* d_out, int out_size)
{
    const float* x      = (const float*)d_in[0];
    const float* Wq     = (const float*)d_in[1];
    const float* Wk     = (const float*)d_in[2];
    const float* Wv     = (const float*)d_in[3];
    const float* Wproj  = (const float*)d_in[4];
    const float* bproj  = (const float*)d_in[5];
    const float* pos_w  = (const float*)d_in[6];
    const float* pos_b  = (const float*)d_in[7];
    const float* gating = (const float*)d_in[8];
    float* out = (float*)d_out;

    const size_t attn_smem = ATTN_SMEM_WORDS * sizeof(u32);   // ~184 KB
    cudaFuncSetAttribute(attn_kernel, cudaFuncAttributeMaxDynamicSharedMemorySize,
                         (int)attn_smem);
    cudaFuncSetAttribute(qkv_mma_kernel, cudaFuncAttributeMaxDynamicSharedMemorySize,
                         GEMM_SMEM_BYTES);
    cudaFuncSetAttribute(proj_mma_kernel, cudaFuncAttributeMaxDynamicSharedMemorySize,
                         GEMM_SMEM_BYTES);

    qkv_mma_kernel<<<dim3(B_ * N_ / 128, C_ / 128, 3), 256, GEMM_SMEM_BYTES>>>(x, Wq, Wk, Wv);
    pos_kernel<<<(H_ * N_) / 8, 256>>>(pos_w, pos_b);
    attn_kernel<<<dim3(N_ / AROWS, H_, B_), ATHREADS, attn_smem>>>(gating);
    proj_mma_kernel<<<dim3(B_ * N_ / 128, C_ / 128), 256, GEMM_SMEM_BYTES>>>(Wproj, bproj, out);
}

// round 13
// speedup vs baseline: 3.9665x; 1.0430x over previous
#include <cuda_runtime.h>

typedef unsigned int u32;

// Problem constants (fixed by the dataset)
#define B_  16
#define H_  12
#define N_  576
#define D_  64
#define C_  768
#define GW_ 24

// ---- scratch ----
__device__ float g_Q [B_*H_*N_*D_];
__device__ float g_K [B_*H_*N_*D_];
__device__ float g_V [B_*H_*N_*D_];
__device__ float g_AO[B_*N_*C_];
__device__ float g_SP[H_*N_*N_];      // positional softmax table (L2-resident, 15.9MB)

// ---------------------------------------------------------------------------
// TF32 helpers
// ---------------------------------------------------------------------------
__device__ __forceinline__ u32 f2tf(float f) {
    u32 u;
    asm("cvt.rna.tf32.f32 %0, %1;" : "=r"(u) : "f"(f));
    return u;
}
// Fragment mapping (m16n8k8, verified):
//   A: a0=(m=g,k=tq) a1=(m=g+8,k=tq) a2=(m=g,k=tq+4) a3=(m=g+8,k=tq+4)
//   B: b0=(k=tq,n=g) b1=(k=tq+4,n=g)
//   C: c0=(m=g,n=2tq) c1=(g,2tq+1) c2=(g+8,2tq) c3=(g+8,2tq+1)
__device__ __forceinline__ void mma_tf32(float* d, const u32* a, const u32* b) {
    asm volatile(
        "mma.sync.aligned.m16n8k8.row.col.f32.tf32.tf32.f32 "
        "{%0,%1,%2,%3}, {%4,%5,%6,%7}, {%8,%9}, {%0,%1,%2,%3};"
        : "+f"(d[0]), "+f"(d[1]), "+f"(d[2]), "+f"(d[3])
        : "r"(a[0]), "r"(a[1]), "r"(a[2]), "r"(a[3]), "r"(b[0]), "r"(b[1]));
}

__device__ __forceinline__ uint4 f2tf4(float4 v) {
    uint4 u; u.x = f2tf(v.x); u.y = f2tf(v.y); u.z = f2tf(v.z); u.w = f2tf(v.w);
    return u;
}

// ===========================================================================
// TF32 GEMM core: 128x128 tile, BK=16, 4 warps x (64x64) warp tiles
// (square warp tile minimizes inter-warp fragment redundancy:
//  crossbar bytes/MMA 192->128, balancing LSU vs tensor pipe).
// Double-buffered smem mainloop (one barrier per K-iter).
// Conflict-free layouts: sA [m][68] (banks 4g+tq), sB [k][136] (banks 8tq+g).
// ===========================================================================
#define SA_ST 68
#define SB_ST 136
#define A_WORDS (128 * SA_ST)
#define BUF_WORDS (A_WORDS + 16 * SB_ST)
#define GEMM_SMEM_BYTES (2 * BUF_WORDS * 4)

#define EPI_QKV  0
#define EPI_PROJ 1

template<int EPI>
__device__ __forceinline__ void gemm_tf32_body(
    const float* __restrict__ A, const float* __restrict__ Wm,
    int row0, int col0,
    float* __restrict__ dst, const float* __restrict__ bias)
{
    extern __shared__ __align__(16) u32 dynsm[];

    const int t    = threadIdx.x;        // 0..127
    const int w    = t >> 5;             // 0..3
    const int lane = t & 31;
    const int g    = lane >> 2;
    const int tq   = lane & 3;
    const int m0w  = (w & 1) * 64;
    const int n0w  = (w >> 1) * 64;

    // loaders: A 128x16 = 512 float4 (4/thread), B 16x128 = 512 float4 (4/thread)
    const int ar = t >> 2;               // rows ar + 32*j
    const int ak = (t & 3) * 4;
    const int bk = t >> 5;               // k rows bk + 4*j
    const int bn = (t & 31) * 4;

    float acc[4][8][4] = {};
    float4 ra[4], rb[4];

    #pragma unroll
    for (int j = 0; j < 4; j++) {
        ra[j] = *(const float4*)&A [(row0 + ar + 32 * j) * C_ + ak];
        rb[j] = *(const float4*)&Wm[(bk + 4 * j) * C_ + col0 + bn];
    }
    {
        u32* sA = dynsm;
        u32* sB = dynsm + A_WORDS;
        #pragma unroll
        for (int j = 0; j < 4; j++) {
            *(uint4*)&sA[(ar + 32 * j) * SA_ST + ak] = f2tf4(ra[j]);
            *(uint4*)&sB[(bk + 4 * j ) * SB_ST + bn] = f2tf4(rb[j]);
        }
    }
    #pragma unroll
    for (int j = 0; j < 4; j++) {
        ra[j] = *(const float4*)&A [(row0 + ar + 32 * j) * C_ + 16 + ak];
        rb[j] = *(const float4*)&Wm[(16 + bk + 4 * j) * C_ + col0 + bn];
    }
    __syncthreads();

    const int NIT = C_ / 16;
    for (int it = 0; it < NIT; it++) {
        const u32* sA = dynsm + (it & 1) * BUF_WORDS;
        const u32* sB = sA + A_WORDS;

        #pragma unroll
        for (int ks = 0; ks < 16; ks += 8) {
            u32 af[4][4], bf[8][2];
            #pragma unroll
            for (int mb = 0; mb < 4; mb++) {
                int mrow = m0w + mb * 16 + g;
                af[mb][0] = sA[(mrow    ) * SA_ST + ks + tq    ];
                af[mb][1] = sA[(mrow + 8) * SA_ST + ks + tq    ];
                af[mb][2] = sA[(mrow    ) * SA_ST + ks + tq + 4];
                af[mb][3] = sA[(mrow + 8) * SA_ST + ks + tq + 4];
            }
            #pragma unroll
            for (int nb = 0; nb < 8; nb++) {
                int nc = n0w + nb * 8 + g;
                bf[nb][0] = sB[(ks + tq    ) * SB_ST + nc];
                bf[nb][1] = sB[(ks + tq + 4) * SB_ST + nc];
            }
            #pragma unroll
            for (int mb = 0; mb < 4; mb++)
                #pragma unroll
                for (int nb = 0; nb < 8; nb++)
                    mma_tf32(acc[mb][nb], af[mb], bf[nb]);
        }

        if (it + 1 < NIT) {
            u32* nA = dynsm + ((it + 1) & 1) * BUF_WORDS;
            u32* nB = nA + A_WORDS;
            #pragma unroll
            for (int j = 0; j < 4; j++) {
                *(uint4*)&nA[(ar + 32 * j) * SA_ST + ak] = f2tf4(ra[j]);
                *(uint4*)&nB[(bk + 4 * j ) * SB_ST + bn] = f2tf4(rb[j]);
            }
            if (it + 2 < NIT) {
                int k0 = (it + 2) * 16;
                #pragma unroll
                for (int j = 0; j < 4; j++) {
                    ra[j] = *(const float4*)&A [(row0 + ar + 32 * j) * C_ + k0 + ak];
                    rb[j] = *(const float4*)&Wm[(k0 + bk + 4 * j) * C_ + col0 + bn];
                }
            }
        }
        __syncthreads();
    }

    // epilogue: float2 stores (cols 2tq, 2tq+1 adjacent)
    #pragma unroll
    for (int mb = 0; mb < 4; mb++) {
        int r0 = row0 + m0w + mb * 16 + g;
        #pragma unroll
        for (int nb = 0; nb < 8; nb++) {
            int c0 = col0 + n0w + nb * 8 + 2 * tq;
            #pragma unroll
            for (int rr = 0; rr < 2; rr++) {
                int row = r0 + rr * 8;
                float2 v;
                v.x = acc[mb][nb][rr * 2 + 0];
                v.y = acc[mb][nb][rr * 2 + 1];
                if (EPI == EPI_QKV) {
                    int b  = row / N_;
                    int n  = row - b * N_;
                    int hh = c0 >> 6;
                    int dd = c0 & 63;
                    *(float2*)&dst[(((b * H_ + hh) * N_) + n) * D_ + dd] = v;
                } else {
                    v.x += bias[c0];
                    v.y += bias[c0 + 1];
                    *(float2*)&dst[(size_t)row * C_ + c0] = v;
                }
            }
        }
    }
}

__global__ __launch_bounds__(128, 2) void qkv_mma_kernel(
    const float* __restrict__ x,
    const float* __restrict__ Wq,
    const float* __restrict__ Wk,
    const float* __restrict__ Wv)
{
    const float* W   = (blockIdx.z == 0) ? Wq : (blockIdx.z == 1) ? Wk : Wv;
    float*       dst = (blockIdx.z == 0) ? g_Q : (blockIdx.z == 1) ? g_K : g_V;
    gemm_tf32_body<EPI_QKV>(x, W, blockIdx.x * 128, blockIdx.y * 128, dst, 0);
}

__global__ __launch_bounds__(128, 2) void proj_mma_kernel(
    const float* __restrict__ Wproj,
    const float* __restrict__ bproj,
    float* __restrict__ out)
{
    gemm_tf32_body<EPI_PROJ>(g_AO, Wproj, blockIdx.x * 128, blockIdx.y * 128,
                             out, bproj);
}

// ===========================================================================
// K2: positional softmax table S_pos[h][n][m]. One warp per (h,n) row.
// ===========================================================================
__global__ __launch_bounds__(256) void pos_kernel(
    const float* __restrict__ pos_w,
    const float* __restrict__ pos_b)
{
    const int warp = threadIdx.x >> 5;
    const int lane = threadIdx.x & 31;
    const int row  = blockIdx.x * 8 + warp;
    const int h    = row / N_;
    const int n    = row - h * N_;

    const float wx = pos_w[0 * H_ + h];
    const float wy = pos_w[1 * H_ + h];
    const float wz = pos_w[2 * H_ + h];
    const float pb = pos_b[h];
    const int nx = n % GW_, ny = n / GW_;

    float buf[18];
    float mx = -1e30f;
    #pragma unroll
    for (int i = 0; i < 18; i++) {
        int m  = lane + 32 * i;
        float fdx = (float)((m % GW_) - nx);
        float fdy = (float)((m / GW_) - ny);
        float s = wx * fdx + wy * fdy + wz * (fdx * fdx + fdy * fdy) + pb;
        buf[i] = s;
        mx = fmaxf(mx, s);
    }
    #pragma unroll
    for (int o = 16; o; o >>= 1) mx = fmaxf(mx, __shfl_xor_sync(0xffffffffu, mx, o));

    float sum = 0.f;
    #pragma unroll
    for (int i = 0; i < 18; i++) { buf[i] = __expf(buf[i] - mx); sum += buf[i]; }
    #pragma unroll
    for (int o = 16; o; o >>= 1) sum += __shfl_xor_sync(0xffffffffu, sum, o);

    const float inv = 1.f / sum;
    float* dstp = g_SP + (size_t)row * N_;
    #pragma unroll
    for (int i = 0; i < 18; i++) dstp[lane + 32 * i] = buf[i] * inv;
}

// ===========================================================================
// K3: fused attention, TF32 MMA, 64 query rows per block (512 threads).
// ===========================================================================
#define SQ_ST 68
#define SK_ST 68
#define SV_ST 72
#define SS_ST 580
#define AROWS 64
#define ATHREADS 512
#define ATTN_SMEM_WORDS (AROWS*SQ_ST + AROWS*SV_ST + AROWS*SS_ST)

__global__ __launch_bounds__(ATHREADS, 1) void attn_kernel(const float* __restrict__ gating)
{
    extern __shared__ __align__(16) u32 smw[];
    u32*   sQ   = smw;                           // tf32 [64][SQ_ST]
    u32*   sKV  = sQ + AROWS * SQ_ST;            // tf32 K [64][SK_ST] / V [64][SV_ST]
    float* sS   = (float*)(sKV + AROWS * SV_ST); // fp32 scores -> tf32 weights [64][SS_ST]
    u32*   sSw  = (u32*)sS;

    const int b  = blockIdx.z;
    const int h  = blockIdx.y;
    const int n0 = blockIdx.x * AROWS;
    const int t  = threadIdx.x;
    const int w    = t >> 5;
    const int lane = t & 31;
    const int g    = lane >> 2;
    const int tq   = lane & 3;
    const int roff = (w & 3) * 16;     // row half: 0,16,32,48
    const int cg   = (w >> 2) * 16;    // col group within 64

    const float* Qp = g_Q + (((size_t)(b * H_ + h)) * N_ + n0) * D_;
    const float* Kp = g_K + ((size_t)(b * H_ + h)) * N_ * D_;
    const float* Vp = g_V + ((size_t)(b * H_ + h)) * N_ * D_;

    const int lr0 = t >> 4;            // rows lr0, lr0+32
    const int ld4 = (t & 15) << 2;

    *(uint4*)&sQ[(lr0     ) * SQ_ST + ld4] = f2tf4(*(const float4*)&Qp[(lr0     ) * D_ + ld4]);
    *(uint4*)&sQ[(lr0 + 32) * SQ_ST + ld4] = f2tf4(*(const float4*)&Qp[(lr0 + 32) * D_ + ld4]);
    __syncthreads();

    u32 qf[8][4];
    #pragma unroll
    for (int ks = 0; ks < 8; ks++) {
        int k0 = ks * 8;
        qf[ks][0] = sQ[(roff + g    ) * SQ_ST + k0 + tq    ];
        qf[ks][1] = sQ[(roff + g + 8) * SQ_ST + k0 + tq    ];
        qf[ks][2] = sQ[(roff + g    ) * SQ_ST + k0 + tq + 4];
        qf[ks][3] = sQ[(roff + g + 8) * SQ_ST + k0 + tq + 4];
    }

    // ---------------- Phase A: scores via MMA (prefetched K tiles) ---------
    float4 pre0 = *(const float4*)&Kp[(lr0     ) * D_ + ld4];
    float4 pre1 = *(const float4*)&Kp[(lr0 + 32) * D_ + ld4];

    for (int tile = 0; tile < 9; tile++) {
        const int m0 = tile * 64;
        __syncthreads();
        *(uint4*)&sKV[(lr0     ) * SK_ST + ld4] = f2tf4(pre0);
        *(uint4*)&sKV[(lr0 + 32) * SK_ST + ld4] = f2tf4(pre1);
        if (tile < 8) {
            const float* Kn = Kp + (m0 + 64) * D_;
            pre0 = *(const float4*)&Kn[(lr0     ) * D_ + ld4];
            pre1 = *(const float4*)&Kn[(lr0 + 32) * D_ + ld4];
        }
        __syncthreads();

        float acc[2][4] = {};
        #pragma unroll
        for (int ks = 0; ks < 8; ks++) {
            int k0 = ks * 8;
            #pragma unroll
            for (int nt = 0; nt < 2; nt++) {
                int nb = cg + nt * 8;
                u32 bfr[2];
                bfr[0] = sKV[(nb + g) * SK_ST + k0 + tq    ];
                bfr[1] = sKV[(nb + g) * SK_ST + k0 + tq + 4];
                mma_tf32(acc[nt], qf[ks], bfr);
            }
        }
        #pragma unroll
        for (int nt = 0; nt < 2; nt++) {
            int c0 = m0 + cg + nt * 8 + 2 * tq;
            float2 v0; v0.x = acc[nt][0] * 0.125f; v0.y = acc[nt][1] * 0.125f;
            float2 v1; v1.x = acc[nt][2] * 0.125f; v1.y = acc[nt][3] * 0.125f;
            *(float2*)&sS[(roff + g    ) * SS_ST + c0] = v0;
            *(float2*)&sS[(roff + g + 8) * SS_ST + c0] = v1;
        }
    }

    pre0 = *(const float4*)&Vp[(lr0     ) * D_ + ld4];
    pre1 = *(const float4*)&Vp[(lr0 + 32) * D_ + ld4];

    __syncthreads();

    // ---------------- Merged softmax + positional blend (tf32 out) ---------
    {
        const float gt = 1.f / (1.f + __expf(-gating[h]));
        const float c1 = 1.f - gt;
        const bool  tail = (lane < 16);

        for (int r = w; r < AROWS; r += 16) {
            float4* rowp4 = (float4*)(sS + r * SS_ST);
            uint4*  rowp4u = (uint4*)rowp4;
            float4 e4[5];
            float mx = -1e30f;
            #pragma unroll
            for (int i = 0; i < 4; i++) {
                e4[i] = rowp4[lane + 32 * i];
                mx = fmaxf(mx, fmaxf(fmaxf(e4[i].x, e4[i].y), fmaxf(e4[i].z, e4[i].w)));
            }
            if (tail) {
                e4[4] = rowp4[128 + lane];
                mx = fmaxf(mx, fmaxf(fmaxf(e4[4].x, e4[4].y), fmaxf(e4[4].z, e4[4].w)));
            } else {
                e4[4].x = e4[4].y = e4[4].z = e4[4].w = -1e30f;
            }
            #pragma unroll
            for (int o = 16; o; o >>= 1) mx = fmaxf(mx, __shfl_xor_sync(0xffffffffu, mx, o));

            float sum = 0.f;
            #pragma unroll
            for (int i = 0; i < 5; i++) {
                e4[i].x = __expf(e4[i].x - mx);
                e4[i].y = __expf(e4[i].y - mx);
                e4[i].z = __expf(e4[i].z - mx);
                e4[i].w = __expf(e4[i].w - mx);
                sum += (e4[i].x + e4[i].y) + (e4[i].z + e4[i].w);
            }
            #pragma unroll
            for (int o = 16; o; o >>= 1) sum += __shfl_xor_sync(0xffffffffu, sum, o);
            const float a = c1 / sum;

            const float4* sp4 = (const float4*)(g_SP + ((size_t)h * N_ + n0 + r) * N_);
            #pragma unroll
            for (int i = 0; i < 4; i++) {
                float4 s = sp4[lane + 32 * i];
                uint4 o4;
                o4.x = f2tf(a * e4[i].x + gt * s.x);
                o4.y = f2tf(a * e4[i].y + gt * s.y);
                o4.z = f2tf(a * e4[i].z + gt * s.z);
                o4.w = f2tf(a * e4[i].w + gt * s.w);
                rowp4u[lane + 32 * i] = o4;
            }
            if (tail) {
                float4 s = sp4[128 + lane];
                uint4 o4;
                o4.x = f2tf(a * e4[4].x + gt * s.x);
                o4.y = f2tf(a * e4[4].y + gt * s.y);
                o4.z = f2tf(a * e4[4].z + gt * s.z);
                o4.w = f2tf(a * e4[4].w + gt * s.w);
                rowp4u[128 + lane] = o4;
            }
        }
    }

    // ---------------- Phase D: out = W @ V via MMA --------------------------
    float accD[2][4] = {};
    for (int tile = 0; tile < 9; tile++) {
        const int m0 = tile * 64;
        __syncthreads();
        *(uint4*)&sKV[(lr0     ) * SV_ST + ld4] = f2tf4(pre0);
        *(uint4*)&sKV[(lr0 + 32) * SV_ST + ld4] = f2tf4(pre1);
        if (tile < 8) {
            const float* Vn = Vp + (m0 + 64) * D_;
            pre0 = *(const float4*)&Vn[(lr0     ) * D_ + ld4];
            pre1 = *(const float4*)&Vn[(lr0 + 32) * D_ + ld4];
        }
        __syncthreads();

        #pragma unroll
        for (int ks = 0; ks < 8; ks++) {
            int k0 = m0 + ks * 8;
            u32 a[4];
            a[0] = sSw[(roff + g    ) * SS_ST + k0 + tq    ];
            a[1] = sSw[(roff + g + 8) * SS_ST + k0 + tq    ];
            a[2] = sSw[(roff + g    ) * SS_ST + k0 + tq + 4];
            a[3] = sSw[(roff + g + 8) * SS_ST + k0 + tq + 4];
            #pragma unroll
            for (int nt = 0; nt < 2; nt++) {
                int nb = cg + nt * 8;
                u32 bfr[2];
                bfr[0] = sKV[(ks * 8 + tq    ) * SV_ST + nb + g];
                bfr[1] = sKV[(ks * 8 + tq + 4) * SV_ST + nb + g];
                mma_tf32(accD[nt], a, bfr);
            }
        }
    }

    float* Op = g_AO + ((size_t)(b * N_ + n0)) * C_ + h * D_;
    #pragma unroll
    for (int nt = 0; nt < 2; nt++) {
        int c0 = cg + nt * 8 + 2 * tq;
        float2 v0; v0.x = accD[nt][0]; v0.y = accD[nt][1];
        float2 v1; v1.x = accD[nt][2]; v1.y = accD[nt][3];
        *(float2*)&Op[(roff + g    ) * C_ + c0] = v0;
        *(float2*)&Op[(roff + g + 8) * C_ + c0] = v1;
    }
}

// ===========================================================================
extern "C" void kernel_launch(void* const* d_in, const int* in_sizes, int n_in,
                              void* d_out, int out_size)
{
    const float* x      = (const float*)d_in[0];
    const float* Wq     = (const float*)d_in[1];
    const float* Wk     = (const float*)d_in[2];
    const float* Wv     = (const float*)d_in[3];
    const float* Wproj  = (const float*)d_in[4];
    const float* bproj  = (const float*)d_in[5];
    const float* pos_w  = (const float*)d_in[6];
    const float* pos_b  = (const float*)d_in[7];
    const float* gating = (const float*)d_in[8];
    float* out = (float*)d_out;

    const size_t attn_smem = ATTN_SMEM_WORDS * sizeof(u32);   // ~184 KB
    cudaFuncSetAttribute(attn_kernel, cudaFuncAttributeMaxDynamicSharedMemorySize,
                         (int)attn_smem);
    cudaFuncSetAttribute(qkv_mma_kernel, cudaFuncAttributeMaxDynamicSharedMemorySize,
                         GEMM_SMEM_BYTES);
    cudaFuncSetAttribute(proj_mma_kernel, cudaFuncAttributeMaxDynamicSharedMemorySize,
                         GEMM_SMEM_BYTES);

    qkv_mma_kernel<<<dim3(B_ * N_ / 128, C_ / 128, 3), 128, GEMM_SMEM_BYTES>>>(x, Wq, Wk, Wv);
    pos_kernel<<<(H_ * N_) / 8, 256>>>(pos_w, pos_b);
    attn_kernel<<<dim3(N_ / AROWS, H_, B_), ATHREADS, attn_smem>>>(gating);
    proj_mma_kernel<<<dim3(B_ * N_ / 128, C_ / 128), 128, GEMM_SMEM_BYTES>>>(Wproj, bproj, out);
}